// round 6
// baseline (speedup 1.0000x reference)
#include <cuda_runtime.h>
#include <cuda_bf16.h>
#include <math.h>
#include <stdint.h>

// ---------------- problem constants ----------------
#define Bn      2
#define Cn      256
#define Hn      256
#define Wn      256
#define HEADS   4
#define CH      64
#define WSZ     8
#define NH      32
#define NWIN    1024
#define WINSZ   64
#define NWF     307
#define NSEL    614
#define SRn     8
#define H1      32
#define HW1     1024
#define NTOK    (NSEL*WINSZ)   // 39296
#define GTOK    (Bn*HW1)       // 2048
#define SCALE   0.125f
#define GK      256
#define PPB     154            // window pairs per batch = ceil(307/2)

// ---------------- scratch ----------------
__device__ float d_wf[NTOK * Cn];
__device__ float d_q [NTOK * Cn];
__device__ float d_kv[NTOK * 2 * Cn];
__device__ float d_g [GTOK * Cn];
__device__ int   d_sel[NSEL];
__device__ float d_wtql [Cn * Cn];
__device__ float d_wtkvl[2 * Cn * Cn];
__device__ float d_wtqg [Cn * Cn];
__device__ float d_wtkvg[2 * Cn * Cn];
__device__ float d_wtp  [Cn * Cn];

// ---------------- mma helpers ----------------
__device__ __forceinline__ uint32_t f2tf(float x) {
    uint32_t r;
    asm("cvt.rna.tf32.f32 %0, %1;" : "=r"(r) : "f"(x));
    return r;
}
__device__ __forceinline__ void mma_tf32(float d[4], const uint32_t a[4], const uint32_t b[2]) {
    asm volatile(
        "mma.sync.aligned.m16n8k8.row.col.f32.tf32.tf32.f32 "
        "{%0,%1,%2,%3}, {%4,%5,%6,%7}, {%8,%9}, {%0,%1,%2,%3};"
        : "+f"(d[0]), "+f"(d[1]), "+f"(d[2]), "+f"(d[3])
        : "r"(a[0]), "r"(a[1]), "r"(a[2]), "r"(a[3]), "r"(b[0]), "r"(b[1]));
}

// ============================================================
// 0) all weight transposes in one launch: WT[n][k] = W[k][n]
// ============================================================
__global__ void transpose_all_kernel(
    const float* __restrict__ w0, const float* __restrict__ w1,
    const float* __restrict__ w2, const float* __restrict__ w3,
    const float* __restrict__ w4,
    float* __restrict__ t0, float* __restrict__ t1,
    float* __restrict__ t2, float* __restrict__ t3,
    float* __restrict__ t4) {
    __shared__ float t[32][33];
    const float* W; float* WT; int N;
    switch (blockIdx.z) {
        case 0:  W = w0; WT = t0; N = Cn;     break;
        case 1:  W = w1; WT = t1; N = 2 * Cn; break;
        case 2:  W = w2; WT = t2; N = Cn;     break;
        case 3:  W = w3; WT = t3; N = 2 * Cn; break;
        default: W = w4; WT = t4; N = Cn;     break;
    }
    int kx = blockIdx.x * 32, nx = blockIdx.y * 32;
    if (nx >= N) return;
    for (int r = threadIdx.y; r < 32; r += 8)
        t[r][threadIdx.x] = W[(size_t)(kx + r) * N + nx + threadIdx.x];
    __syncthreads();
    for (int r = threadIdx.y; r < 32; r += 8)
        WT[(size_t)(nx + r) * GK + kx + threadIdx.x] = t[threadIdx.x][r];
}

// ============================================================
// 1) top-k window selection
// ============================================================
__global__ void select_kernel(const float* __restrict__ unc, int* __restrict__ sel) {
    __shared__ float sc[NWIN];
    int b  = blockIdx.x;
    int wi = threadIdx.x;
    int wh = wi >> 5, ww = wi & 31;
    const float* u = unc + ((size_t)b * Hn + wh * WSZ) * Wn + ww * WSZ;
    float s = 0.f;
    #pragma unroll
    for (int i = 0; i < WSZ; i++)
        #pragma unroll
        for (int j = 0; j < WSZ; j++)
            s += u[i * Wn + j];
    sc[wi] = s;
    __syncthreads();
    int rank = 0;
    for (int j = 0; j < NWIN; j++) {
        float sj = sc[j];
        rank += (sj > s) || (sj == s && j < wi);
    }
    if (rank < NWF) sel[b * NWF + rank] = wi;
}

// ============================================================
// 2) gather selected windows
// ============================================================
__global__ void gather_kernel(const float* __restrict__ feat, const int* __restrict__ sel,
                              float* __restrict__ wf) {
    int n = blockIdx.x;
    int c = threadIdx.x;
    int b = n / NWF;
    int wi = sel[n];
    int wh = wi >> 5, ww = wi & 31;
    const float* src = feat + (((size_t)b * Cn + c) * Hn + wh * WSZ) * Wn + ww * WSZ;
    float* dst = wf + (size_t)n * WINSZ * Cn + c;
    #pragma unroll
    for (int p = 0; p < WINSZ; p++)
        dst[p * Cn] = src[(p >> 3) * Wn + (p & 7)];
}

// ============================================================
// 3) tf32 mma.sync GEMM:  tile 128x256, 8 warps = 2m x 4n,
//    warp = 64x64 = 4x8 m16n8k8 fragments. Dynamic smem 54KB.
// ============================================================
#define GEMM_SMEM ((128 + 256) * 36 * 4)   // 55296

__global__ __launch_bounds__(256)
void mma_gemm_kernel(const float* __restrict__ A, const float* __restrict__ WT,
                     float* __restrict__ C, const float* __restrict__ bias, int ldc) {
    extern __shared__ uint32_t sg[];
    uint32_t* As = sg;              // [128][36]
    uint32_t* Bs = sg + 128 * 36;   // [256][36]

    int tid = threadIdx.x;
    int lane = tid & 31, wid = tid >> 5;
    int g = lane >> 2, t = lane & 3;
    int wm = wid & 1, wn = wid >> 1;
    int m0 = blockIdx.x * 128, n0 = blockIdx.y * 256;

    float acc[4][8][4] = {};

    for (int kc = 0; kc < GK; kc += 32) {
        for (int i = tid; i < 1024; i += 256) {
            int r = i >> 3, q4 = (i & 7) << 2;
            float4 v = *(const float4*)(A + (size_t)(m0 + r) * GK + kc + q4);
            uint32_t* d = As + r * 36 + q4;
            d[0] = f2tf(v.x); d[1] = f2tf(v.y); d[2] = f2tf(v.z); d[3] = f2tf(v.w);
        }
        for (int i = tid; i < 2048; i += 256) {
            int r = i >> 3, q4 = (i & 7) << 2;
            float4 v = *(const float4*)(WT + (size_t)(n0 + r) * GK + kc + q4);
            uint32_t* d = Bs + r * 36 + q4;
            d[0] = f2tf(v.x); d[1] = f2tf(v.y); d[2] = f2tf(v.z); d[3] = f2tf(v.w);
        }
        __syncthreads();

        #pragma unroll
        for (int ks = 0; ks < 4; ks++) {
            uint32_t af[4][4];
            #pragma unroll
            for (int mf = 0; mf < 4; mf++) {
                int rb = wm * 64 + mf * 16;
                af[mf][0] = As[(rb + g    ) * 36 + ks * 8 + t];
                af[mf][1] = As[(rb + g + 8) * 36 + ks * 8 + t];
                af[mf][2] = As[(rb + g    ) * 36 + ks * 8 + t + 4];
                af[mf][3] = As[(rb + g + 8) * 36 + ks * 8 + t + 4];
            }
            #pragma unroll
            for (int nf = 0; nf < 8; nf++) {
                int nb = wn * 64 + nf * 8;
                uint32_t bf[2];
                bf[0] = Bs[(nb + g) * 36 + ks * 8 + t];
                bf[1] = Bs[(nb + g) * 36 + ks * 8 + t + 4];
                #pragma unroll
                for (int mf = 0; mf < 4; mf++)
                    mma_tf32(acc[mf][nf], af[mf], bf);
            }
        }
        __syncthreads();
    }

    #pragma unroll
    for (int mf = 0; mf < 4; mf++) {
        int r0 = m0 + wm * 64 + mf * 16 + g;
        #pragma unroll
        for (int nf = 0; nf < 8; nf++) {
            int cc = n0 + wn * 64 + nf * 8 + 2 * t;
            float b0 = 0.f, b1 = 0.f;
            if (bias) { b0 = __ldg(&bias[cc]); b1 = __ldg(&bias[cc + 1]); }
            float2 v0 = { acc[mf][nf][0] + b0, acc[mf][nf][1] + b1 };
            float2 v1 = { acc[mf][nf][2] + b0, acc[mf][nf][3] + b1 };
            *(float2*)(C + (size_t)r0 * ldc + cc)       = v0;
            *(float2*)(C + (size_t)(r0 + 8) * ldc + cc) = v1;
        }
    }
}

// ============================================================
// 4a) local window attention (tf32 mma), 128 threads, 1 window
// ============================================================
#define AS_STR 68
#define ATTL_SMEM (3 * 64 * AS_STR * 4)   // 52224

__global__ __launch_bounds__(128)
void attn_local_kernel(const float* __restrict__ Q, const float* __restrict__ KV,
                       float* __restrict__ wfacc) {
    extern __shared__ uint32_t smu[];
    uint32_t* Ks = smu;
    uint32_t* Vs = Ks + 64 * AS_STR;
    uint32_t* Ps = Vs + 64 * AS_STR;

    int n = blockIdx.x, h = blockIdx.y;
    int tid = threadIdx.x;
    int lane = tid & 31, w = tid >> 5;
    int g = lane >> 2, t = lane & 3;
    int qtok0 = n * WINSZ;
    int kbase = n * WINSZ;
    int qrow0 = w * 16;

    uint32_t qf[8][4];
    {
        const float* qb = Q + (size_t)(qtok0 + qrow0) * Cn + h * CH;
        #pragma unroll
        for (int ks = 0; ks < 8; ks++) {
            qf[ks][0] = f2tf(qb[(size_t)(g    ) * Cn + ks * 8 + t    ] * SCALE);
            qf[ks][1] = f2tf(qb[(size_t)(g + 8) * Cn + ks * 8 + t    ] * SCALE);
            qf[ks][2] = f2tf(qb[(size_t)(g    ) * Cn + ks * 8 + t + 4] * SCALE);
            qf[ks][3] = f2tf(qb[(size_t)(g + 8) * Cn + ks * 8 + t + 4] * SCALE);
        }
    }

    for (int i = tid; i < 1024; i += 128) {
        int tok = i >> 4, c4 = (i & 15) << 2;
        const float* base = KV + (size_t)(kbase + tok) * (2 * Cn) + h * CH;
        float4 kv4 = *(const float4*)(base + c4);
        float4 vv4 = *(const float4*)(base + Cn + c4);
        uint32_t* kd = Ks + tok * AS_STR + c4;
        uint32_t* vd = Vs + tok * AS_STR + c4;
        kd[0] = f2tf(kv4.x); kd[1] = f2tf(kv4.y); kd[2] = f2tf(kv4.z); kd[3] = f2tf(kv4.w);
        vd[0] = f2tf(vv4.x); vd[1] = f2tf(vv4.y); vd[2] = f2tf(vv4.z); vd[3] = f2tf(vv4.w);
    }
    __syncthreads();

    float ss[8][4] = {};
    #pragma unroll
    for (int nf = 0; nf < 8; nf++) {
        #pragma unroll
        for (int ks = 0; ks < 8; ks++) {
            uint32_t bf[2];
            bf[0] = Ks[(nf * 8 + g) * AS_STR + ks * 8 + t];
            bf[1] = Ks[(nf * 8 + g) * AS_STR + ks * 8 + t + 4];
            mma_tf32(ss[nf], qf[ks], bf);
        }
    }

    float cm0 = -1e30f, cm1 = -1e30f;
    #pragma unroll
    for (int nf = 0; nf < 8; nf++) {
        cm0 = fmaxf(cm0, fmaxf(ss[nf][0], ss[nf][1]));
        cm1 = fmaxf(cm1, fmaxf(ss[nf][2], ss[nf][3]));
    }
    cm0 = fmaxf(cm0, __shfl_xor_sync(0xffffffffu, cm0, 1));
    cm0 = fmaxf(cm0, __shfl_xor_sync(0xffffffffu, cm0, 2));
    cm1 = fmaxf(cm1, __shfl_xor_sync(0xffffffffu, cm1, 1));
    cm1 = fmaxf(cm1, __shfl_xor_sync(0xffffffffu, cm1, 2));
    float sum0 = 0.f, sum1 = 0.f;
    #pragma unroll
    for (int nf = 0; nf < 8; nf++) {
        ss[nf][0] = __expf(ss[nf][0] - cm0);
        ss[nf][1] = __expf(ss[nf][1] - cm0);
        ss[nf][2] = __expf(ss[nf][2] - cm1);
        ss[nf][3] = __expf(ss[nf][3] - cm1);
        sum0 += ss[nf][0] + ss[nf][1];
        sum1 += ss[nf][2] + ss[nf][3];
    }
    sum0 += __shfl_xor_sync(0xffffffffu, sum0, 1);
    sum0 += __shfl_xor_sync(0xffffffffu, sum0, 2);
    sum1 += __shfl_xor_sync(0xffffffffu, sum1, 1);
    sum1 += __shfl_xor_sync(0xffffffffu, sum1, 2);

    #pragma unroll
    for (int nf = 0; nf < 8; nf++) {
        int pc = nf * 8 + 2 * t;
        uint32_t* p0 = Ps + (qrow0 + g) * AS_STR + pc;
        uint32_t* p1 = Ps + (qrow0 + g + 8) * AS_STR + pc;
        p0[0] = f2tf(ss[nf][0]); p0[1] = f2tf(ss[nf][1]);
        p1[0] = f2tf(ss[nf][2]); p1[1] = f2tf(ss[nf][3]);
    }
    __syncwarp();

    float of[8][4] = {};
    #pragma unroll
    for (int ks2 = 0; ks2 < 8; ks2++) {
        uint32_t pa[4];
        pa[0] = Ps[(qrow0 + g    ) * AS_STR + ks2 * 8 + t];
        pa[1] = Ps[(qrow0 + g + 8) * AS_STR + ks2 * 8 + t];
        pa[2] = Ps[(qrow0 + g    ) * AS_STR + ks2 * 8 + t + 4];
        pa[3] = Ps[(qrow0 + g + 8) * AS_STR + ks2 * 8 + t + 4];
        #pragma unroll
        for (int nf2 = 0; nf2 < 8; nf2++) {
            uint32_t bf[2];
            bf[0] = Vs[(ks2 * 8 + t    ) * AS_STR + nf2 * 8 + g];
            bf[1] = Vs[(ks2 * 8 + t + 4) * AS_STR + nf2 * 8 + g];
            mma_tf32(of[nf2], pa, bf);
        }
    }

    float inv0 = 1.f / sum0, inv1 = 1.f / sum1;
    #pragma unroll
    for (int nf = 0; nf < 8; nf++) {
        float* p0 = wfacc + (size_t)(qtok0 + qrow0 + g) * Cn + h * CH + nf * 8 + 2 * t;
        float* p1 = wfacc + (size_t)(qtok0 + qrow0 + g + 8) * Cn + h * CH + nf * 8 + 2 * t;
        float2 o0 = *(float2*)p0;
        float2 o1 = *(float2*)p1;
        o0.x += of[nf][0] * inv0; o0.y += of[nf][1] * inv0;
        o1.x += of[nf][2] * inv1; o1.y += of[nf][3] * inv1;
        *(float2*)p0 = o0;
        *(float2*)p1 = o1;
    }
}

// ============================================================
// 4b) global cross-attention: 2 windows / block, 256 threads,
//     8 warps x 16 query rows, shared K/V, 16 chunks of 64 keys
// ============================================================
#define ATTG_SMEM ((64 + 64 + 128) * AS_STR * 4)   // 69632

__global__ __launch_bounds__(256)
void attn_global_kernel(const float* __restrict__ Q, const float* __restrict__ KV,
                        float* __restrict__ wfacc) {
    extern __shared__ uint32_t smu[];
    uint32_t* Ks = smu;                    // [64][68]
    uint32_t* Vs = Ks + 64 * AS_STR;       // [64][68]
    uint32_t* Ps = Vs + 64 * AS_STR;       // [128][68]

    int b = blockIdx.x / PPB, pb = blockIdx.x % PPB;
    int h = blockIdx.y;
    int s0 = b * NWF + pb * 2;
    bool has2 = (pb * 2 + 1) < NWF;

    int tid = threadIdx.x;
    int lane = tid & 31, w = tid >> 5;
    int g = lane >> 2, t = lane & 3;
    int qrow0 = w * 16;                          // 0..112
    int myslot = (qrow0 < 64) ? s0 : (has2 ? s0 + 1 : s0);
    bool wb = (qrow0 < 64) || has2;
    int qtok0 = myslot * WINSZ + (qrow0 & 63);
    int kbase = b * HW1;

    uint32_t qf[8][4];
    {
        const float* qb = Q + (size_t)qtok0 * Cn + h * CH;
        #pragma unroll
        for (int ks = 0; ks < 8; ks++) {
            qf[ks][0] = f2tf(qb[(size_t)(g    ) * Cn + ks * 8 + t    ] * SCALE);
            qf[ks][1] = f2tf(qb[(size_t)(g + 8) * Cn + ks * 8 + t    ] * SCALE);
            qf[ks][2] = f2tf(qb[(size_t)(g    ) * Cn + ks * 8 + t + 4] * SCALE);
            qf[ks][3] = f2tf(qb[(size_t)(g + 8) * Cn + ks * 8 + t + 4] * SCALE);
        }
    }

    float of[8][4] = {};
    float rm0 = -1e30f, rm1 = -1e30f, rl0 = 0.f, rl1 = 0.f;

    for (int chk = 0; chk < 16; chk++) {
        __syncthreads();
        for (int i = tid; i < 1024; i += 256) {
            int tok = i >> 4, c4 = (i & 15) << 2;
            const float* base = KV + (size_t)(kbase + chk * 64 + tok) * (2 * Cn) + h * CH;
            float4 kv4 = *(const float4*)(base + c4);
            float4 vv4 = *(const float4*)(base + Cn + c4);
            uint32_t* kd = Ks + tok * AS_STR + c4;
            uint32_t* vd = Vs + tok * AS_STR + c4;
            kd[0] = f2tf(kv4.x); kd[1] = f2tf(kv4.y); kd[2] = f2tf(kv4.z); kd[3] = f2tf(kv4.w);
            vd[0] = f2tf(vv4.x); vd[1] = f2tf(vv4.y); vd[2] = f2tf(vv4.z); vd[3] = f2tf(vv4.w);
        }
        __syncthreads();

        float ss[8][4] = {};
        #pragma unroll
        for (int nf = 0; nf < 8; nf++) {
            #pragma unroll
            for (int ks = 0; ks < 8; ks++) {
                uint32_t bf[2];
                bf[0] = Ks[(nf * 8 + g) * AS_STR + ks * 8 + t];
                bf[1] = Ks[(nf * 8 + g) * AS_STR + ks * 8 + t + 4];
                mma_tf32(ss[nf], qf[ks], bf);
            }
        }

        float cm0 = -1e30f, cm1 = -1e30f;
        #pragma unroll
        for (int nf = 0; nf < 8; nf++) {
            cm0 = fmaxf(cm0, fmaxf(ss[nf][0], ss[nf][1]));
            cm1 = fmaxf(cm1, fmaxf(ss[nf][2], ss[nf][3]));
        }
        cm0 = fmaxf(cm0, __shfl_xor_sync(0xffffffffu, cm0, 1));
        cm0 = fmaxf(cm0, __shfl_xor_sync(0xffffffffu, cm0, 2));
        cm1 = fmaxf(cm1, __shfl_xor_sync(0xffffffffu, cm1, 1));
        cm1 = fmaxf(cm1, __shfl_xor_sync(0xffffffffu, cm1, 2));
        float nm0 = fmaxf(rm0, cm0), nm1 = fmaxf(rm1, cm1);
        float scl0 = __expf(rm0 - nm0), scl1 = __expf(rm1 - nm1);
        float sum0 = 0.f, sum1 = 0.f;
        #pragma unroll
        for (int nf = 0; nf < 8; nf++) {
            ss[nf][0] = __expf(ss[nf][0] - nm0);
            ss[nf][1] = __expf(ss[nf][1] - nm0);
            ss[nf][2] = __expf(ss[nf][2] - nm1);
            ss[nf][3] = __expf(ss[nf][3] - nm1);
            sum0 += ss[nf][0] + ss[nf][1];
            sum1 += ss[nf][2] + ss[nf][3];
        }
        sum0 += __shfl_xor_sync(0xffffffffu, sum0, 1);
        sum0 += __shfl_xor_sync(0xffffffffu, sum0, 2);
        sum1 += __shfl_xor_sync(0xffffffffu, sum1, 1);
        sum1 += __shfl_xor_sync(0xffffffffu, sum1, 2);
        rl0 = rl0 * scl0 + sum0;  rm0 = nm0;
        rl1 = rl1 * scl1 + sum1;  rm1 = nm1;
        #pragma unroll
        for (int nf = 0; nf < 8; nf++) {
            of[nf][0] *= scl0; of[nf][1] *= scl0;
            of[nf][2] *= scl1; of[nf][3] *= scl1;
        }

        #pragma unroll
        for (int nf = 0; nf < 8; nf++) {
            int pc = nf * 8 + 2 * t;
            uint32_t* p0 = Ps + (qrow0 + g) * AS_STR + pc;
            uint32_t* p1 = Ps + (qrow0 + g + 8) * AS_STR + pc;
            p0[0] = f2tf(ss[nf][0]); p0[1] = f2tf(ss[nf][1]);
            p1[0] = f2tf(ss[nf][2]); p1[1] = f2tf(ss[nf][3]);
        }
        __syncwarp();

        #pragma unroll
        for (int ks2 = 0; ks2 < 8; ks2++) {
            uint32_t pa[4];
            pa[0] = Ps[(qrow0 + g    ) * AS_STR + ks2 * 8 + t];
            pa[1] = Ps[(qrow0 + g + 8) * AS_STR + ks2 * 8 + t];
            pa[2] = Ps[(qrow0 + g    ) * AS_STR + ks2 * 8 + t + 4];
            pa[3] = Ps[(qrow0 + g + 8) * AS_STR + ks2 * 8 + t + 4];
            #pragma unroll
            for (int nf2 = 0; nf2 < 8; nf2++) {
                uint32_t bf[2];
                bf[0] = Vs[(ks2 * 8 + t    ) * AS_STR + nf2 * 8 + g];
                bf[1] = Vs[(ks2 * 8 + t + 4) * AS_STR + nf2 * 8 + g];
                mma_tf32(of[nf2], pa, bf);
            }
        }
        __syncwarp();
    }

    if (wb) {
        float inv0 = 1.f / rl0, inv1 = 1.f / rl1;
        #pragma unroll
        for (int nf = 0; nf < 8; nf++) {
            float* p0 = wfacc + (size_t)(qtok0 + g) * Cn + h * CH + nf * 8 + 2 * t;
            float* p1 = wfacc + (size_t)(qtok0 + g + 8) * Cn + h * CH + nf * 8 + 2 * t;
            float2 o0 = *(float2*)p0;
            float2 o1 = *(float2*)p1;
            o0.x += of[nf][0] * inv0; o0.y += of[nf][1] * inv0;
            o1.x += of[nf][2] * inv1; o1.y += of[nf][3] * inv1;
            *(float2*)p0 = o0;
            *(float2*)p1 = o1;
        }
    }
}

// ============================================================
// 5) global branch: depthwise conv -> LN -> exact GELU
// ============================================================
__global__ void convlngelu_kernel(const float* __restrict__ feat,
                                  const float* __restrict__ sr_w,
                                  const float* __restrict__ sr_b,
                                  const float* __restrict__ ln_g,
                                  const float* __restrict__ ln_b,
                                  float* __restrict__ g) {
    __shared__ float red[Cn];
    int bt = blockIdx.x;
    int b = bt >> 10, t = bt & 1023;
    int y1 = t >> 5, x1 = t & 31;
    int c = threadIdx.x;

    const float* src = feat + (((size_t)b * Cn + c) * Hn + y1 * SRn) * Wn + x1 * SRn;
    const float* w = sr_w + c * (SRn * SRn);
    float acc = sr_b[c];
    #pragma unroll
    for (int i = 0; i < SRn; i++)
        #pragma unroll
        for (int j = 0; j < SRn; j++)
            acc += src[i * Wn + j] * w[i * SRn + j];

    red[c] = acc;
    __syncthreads();
    for (int off = 128; off > 0; off >>= 1) {
        if (c < off) red[c] += red[c + off];
        __syncthreads();
    }
    float mu = red[0] * (1.f / Cn);
    __syncthreads();
    float dv = acc - mu;
    red[c] = dv * dv;
    __syncthreads();
    for (int off = 128; off > 0; off >>= 1) {
        if (c < off) red[c] += red[c + off];
        __syncthreads();
    }
    float var = red[0] * (1.f / Cn);
    float rs = rsqrtf(var + 1e-5f);
    float xh = dv * rs * ln_g[c] + ln_b[c];
    float gl = 0.5f * xh * (1.f + erff(xh * 0.70710678118654752440f));
    g[(size_t)bt * Cn + c] = gl;
}

// ============================================================
// 6) scatter-add projected windows back into out
// ============================================================
__global__ void scatter_kernel(const float* __restrict__ P, const int* __restrict__ sel,
                               float* __restrict__ out) {
    int n = blockIdx.x;
    int c = threadIdx.x;
    int b = n / NWF;
    int wi = sel[n];
    int wh = wi >> 5, ww = wi & 31;
    const float* src = P + (size_t)n * WINSZ * Cn + c;
    float* dst = out + (((size_t)b * Cn + c) * Hn + wh * WSZ) * Wn + ww * WSZ;
    #pragma unroll
    for (int p = 0; p < WINSZ; p++)
        dst[(p >> 3) * Wn + (p & 7)] += src[p * Cn];
}

// ============================================================
// launch
// ============================================================
extern "C" void kernel_launch(void* const* d_in, const int* in_sizes, int n_in,
                              void* d_out, int out_size) {
    const float* feat  = (const float*)d_in[0];
    const float* unc   = (const float*)d_in[1];
    const float* sr_w  = (const float*)d_in[2];
    const float* sr_b  = (const float*)d_in[3];
    const float* ln_g  = (const float*)d_in[4];
    const float* ln_b  = (const float*)d_in[5];
    const float* wq_l  = (const float*)d_in[6];
    const float* wkv_l = (const float*)d_in[7];
    const float* wq_g  = (const float*)d_in[8];
    const float* wkv_g = (const float*)d_in[9];
    const float* wp    = (const float*)d_in[10];
    const float* bp    = (const float*)d_in[11];
    float* out = (float*)d_out;

    float *wf, *q, *kv, *g;
    float *wtql, *wtkvl, *wtqg, *wtkvg, *wtp;
    int* sel;
    cudaGetSymbolAddress((void**)&wf,    d_wf);
    cudaGetSymbolAddress((void**)&q,     d_q);
    cudaGetSymbolAddress((void**)&kv,    d_kv);
    cudaGetSymbolAddress((void**)&g,     d_g);
    cudaGetSymbolAddress((void**)&sel,   d_sel);
    cudaGetSymbolAddress((void**)&wtql,  d_wtql);
    cudaGetSymbolAddress((void**)&wtkvl, d_wtkvl);
    cudaGetSymbolAddress((void**)&wtqg,  d_wtqg);
    cudaGetSymbolAddress((void**)&wtkvg, d_wtkvg);
    cudaGetSymbolAddress((void**)&wtp,   d_wtp);

    cudaFuncSetAttribute(mma_gemm_kernel, cudaFuncAttributeMaxDynamicSharedMemorySize, GEMM_SMEM);
    cudaFuncSetAttribute(attn_local_kernel, cudaFuncAttributeMaxDynamicSharedMemorySize, ATTL_SMEM);
    cudaFuncSetAttribute(attn_global_kernel, cudaFuncAttributeMaxDynamicSharedMemorySize, ATTG_SMEM);

    cudaMemcpyAsync(out, feat, (size_t)Bn * Cn * Hn * Wn * sizeof(float),
                    cudaMemcpyDeviceToDevice);

    transpose_all_kernel<<<dim3(8, 16, 5), dim3(32, 8)>>>(
        wq_l, wkv_l, wq_g, wkv_g, wp, wtql, wtkvl, wtqg, wtkvg, wtp);

    select_kernel<<<Bn, NWIN>>>(unc, sel);
    gather_kernel<<<NSEL, Cn>>>(feat, sel, wf);

    // local branch
    mma_gemm_kernel<<<dim3(NTOK / 128, 1), 256, GEMM_SMEM>>>(wf, wtql, q, nullptr, Cn);
    mma_gemm_kernel<<<dim3(NTOK / 128, 2), 256, GEMM_SMEM>>>(wf, wtkvl, kv, nullptr, 2 * Cn);
    attn_local_kernel<<<dim3(NSEL, HEADS), 128, ATTL_SMEM>>>(q, kv, wf);

    // global branch
    convlngelu_kernel<<<GTOK, Cn>>>(feat, sr_w, sr_b, ln_g, ln_b, g);
    mma_gemm_kernel<<<dim3(GTOK / 128, 2), 256, GEMM_SMEM>>>(g, wtkvg, kv, nullptr, 2 * Cn);

    mma_gemm_kernel<<<dim3(NTOK / 128, 1), 256, GEMM_SMEM>>>(wf, wtqg, q, nullptr, Cn);
    attn_global_kernel<<<dim3(Bn * PPB, HEADS), 256, ATTG_SMEM>>>(q, kv, wf);

    // projection + scatter
    mma_gemm_kernel<<<dim3(NTOK / 128, 1), 256, GEMM_SMEM>>>(wf, wtp, q, bp, Cn);
    scatter_kernel<<<NSEL, Cn>>>(q, sel, out);
}

// round 7
// speedup vs baseline: 1.2046x; 1.2046x over previous
#include <cuda_runtime.h>
#include <cuda_bf16.h>
#include <math.h>
#include <stdint.h>

// ---------------- problem constants ----------------
#define Bn      2
#define Cn      256
#define Hn      256
#define Wn      256
#define HEADS   4
#define CH      64
#define WSZ     8
#define NH      32
#define NWIN    1024
#define WINSZ   64
#define NWF     307
#define NSEL    614
#define SRn     8
#define H1      32
#define HW1     1024
#define NTOK    (NSEL*WINSZ)   // 39296
#define GTOK    (Bn*HW1)       // 2048
#define SCALE   0.125f
#define GK      256
#define PPB     154

// ---------------- scratch ----------------
__device__ float d_wf[NTOK * Cn];
__device__ float d_q [NTOK * Cn];
__device__ float d_kv[NTOK * 2 * Cn];
__device__ float d_g [GTOK * Cn];
__device__ int   d_sel[NSEL];
__device__ uint32_t d_wtql [Cn * Cn];      // tf32 bits, [n][k]
__device__ uint32_t d_wtkvl[2 * Cn * Cn];
__device__ uint32_t d_wtqg [Cn * Cn];
__device__ uint32_t d_wtkvg[2 * Cn * Cn];
__device__ uint32_t d_wtp  [Cn * Cn];

// ---------------- helpers ----------------
__device__ __forceinline__ uint32_t f2tf(float x) {
    uint32_t r;
    asm("cvt.rna.tf32.f32 %0, %1;" : "=r"(r) : "f"(x));
    return r;
}
__device__ __forceinline__ void mma_tf32(float d[4], const uint32_t a[4], const uint32_t b[2]) {
    asm volatile(
        "mma.sync.aligned.m16n8k8.row.col.f32.tf32.tf32.f32 "
        "{%0,%1,%2,%3}, {%4,%5,%6,%7}, {%8,%9}, {%0,%1,%2,%3};"
        : "+f"(d[0]), "+f"(d[1]), "+f"(d[2]), "+f"(d[3])
        : "r"(a[0]), "r"(a[1]), "r"(a[2]), "r"(a[3]), "r"(b[0]), "r"(b[1]));
}
__device__ __forceinline__ uint32_t smem_u32(const void* p) {
    uint32_t a;
    asm("{ .reg .u64 t; cvta.to.shared.u64 t, %1; cvt.u32.u64 %0, t; }" : "=r"(a) : "l"(p));
    return a;
}
__device__ __forceinline__ void cp_async16(uint32_t saddr, const void* g) {
    asm volatile("cp.async.cg.shared.global [%0], [%1], 16;" :: "r"(saddr), "l"(g));
}
#define CP_COMMIT() asm volatile("cp.async.commit_group;" ::: "memory")
#define CP_WAIT0()  asm volatile("cp.async.wait_group 0;" ::: "memory")
#define CP_WAIT1()  asm volatile("cp.async.wait_group 1;" ::: "memory")

// ============================================================
// 0) weight transpose + tf32 pre-round: WT[n][k] = tf32(W[k][n])
// ============================================================
__global__ void transpose_all_kernel(
    const float* __restrict__ w0, const float* __restrict__ w1,
    const float* __restrict__ w2, const float* __restrict__ w3,
    const float* __restrict__ w4,
    uint32_t* __restrict__ t0, uint32_t* __restrict__ t1,
    uint32_t* __restrict__ t2, uint32_t* __restrict__ t3,
    uint32_t* __restrict__ t4) {
    __shared__ float t[32][33];
    const float* W; uint32_t* WT; int N;
    switch (blockIdx.z) {
        case 0:  W = w0; WT = t0; N = Cn;     break;
        case 1:  W = w1; WT = t1; N = 2 * Cn; break;
        case 2:  W = w2; WT = t2; N = Cn;     break;
        case 3:  W = w3; WT = t3; N = 2 * Cn; break;
        default: W = w4; WT = t4; N = Cn;     break;
    }
    int kx = blockIdx.x * 32, nx = blockIdx.y * 32;
    if (nx >= N) return;
    for (int r = threadIdx.y; r < 32; r += 8)
        t[r][threadIdx.x] = W[(size_t)(kx + r) * N + nx + threadIdx.x];
    __syncthreads();
    for (int r = threadIdx.y; r < 32; r += 8)
        WT[(size_t)(nx + r) * GK + kx + threadIdx.x] = f2tf(t[threadIdx.x][r]);
}

// ============================================================
// 1) top-k window selection
// ============================================================
__global__ void select_kernel(const float* __restrict__ unc, int* __restrict__ sel) {
    __shared__ float sc[NWIN];
    int b  = blockIdx.x;
    int wi = threadIdx.x;
    int wh = wi >> 5, ww = wi & 31;
    const float* u = unc + ((size_t)b * Hn + wh * WSZ) * Wn + ww * WSZ;
    float s = 0.f;
    #pragma unroll
    for (int i = 0; i < WSZ; i++)
        #pragma unroll
        for (int j = 0; j < WSZ; j++)
            s += u[i * Wn + j];
    sc[wi] = s;
    __syncthreads();
    int rank = 0;
    for (int j = 0; j < NWIN; j++) {
        float sj = sc[j];
        rank += (sj > s) || (sj == s && j < wi);
    }
    if (rank < NWF) sel[b * NWF + rank] = wi;
}

// ============================================================
// 2) gather selected windows
// ============================================================
__global__ void gather_kernel(const float* __restrict__ feat, const int* __restrict__ sel,
                              float* __restrict__ wf) {
    int n = blockIdx.x;
    int c = threadIdx.x;
    int b = n / NWF;
    int wi = sel[n];
    int wh = wi >> 5, ww = wi & 31;
    const float* src = feat + (((size_t)b * Cn + c) * Hn + wh * WSZ) * Wn + ww * WSZ;
    float* dst = wf + (size_t)n * WINSZ * Cn + c;
    #pragma unroll
    for (int p = 0; p < WINSZ; p++)
        dst[p * Cn] = src[(p >> 3) * Wn + (p & 7)];
}

// ============================================================
// 3) tf32 mma.sync GEMM, 128x128 tile, BK=32, cp.async 2-stage
//    8 warps = 2m x 4n; warp = 64x32 = 4x4 fragments
// ============================================================
#define ASTG (128 * 36)
#define GEMM_SMEM (4 * ASTG * 4)   // 73728 bytes

__global__ __launch_bounds__(256)
void mma_gemm_kernel(const float* __restrict__ A, const uint32_t* __restrict__ WT,
                     float* __restrict__ C, const float* __restrict__ bias, int ldc) {
    extern __shared__ uint32_t sg[];
    int tid = threadIdx.x;
    int lane = tid & 31, wid = tid >> 5;
    int g = lane >> 2, t = lane & 3;
    int wm = wid & 1, wn = wid >> 1;
    int m0 = blockIdx.x * 128, n0 = blockIdx.y * 128;

    uint32_t sbase = smem_u32(sg);

    // chunk coords for this thread (4 chunks of 16B each for A and B per stage)
    int crow[4], cq4[4];
    #pragma unroll
    for (int u = 0; u < 4; u++) {
        int c = tid + u * 256;
        crow[u] = c >> 3;
        cq4[u]  = (c & 7) << 2;
    }

    // stage loader
    auto load_stage = [&](int kc, int buf) {
        uint32_t a_s = sbase + (uint32_t)(buf * ASTG) * 4u;
        uint32_t b_s = sbase + (uint32_t)((2 + buf) * ASTG) * 4u;
        #pragma unroll
        for (int u = 0; u < 4; u++) {
            int row = crow[u], q4 = cq4[u];
            cp_async16(a_s + (uint32_t)(row * 36 + q4) * 4u,
                       A + (size_t)(m0 + row) * GK + kc + q4);
            cp_async16(b_s + (uint32_t)(row * 36 + q4) * 4u,
                       WT + (size_t)(n0 + row) * GK + kc + q4);
        }
    };

    float acc[4][4][4] = {};

    load_stage(0, 0);
    CP_COMMIT();

    #pragma unroll 1
    for (int st = 0; st < 8; st++) {
        if (st < 7) {
            load_stage((st + 1) * 32, (st + 1) & 1);
            CP_COMMIT();
            CP_WAIT1();
        } else {
            CP_WAIT0();
        }
        __syncthreads();

        const uint32_t* Asb = sg + (st & 1) * ASTG;
        const uint32_t* Bsb = sg + (2 + (st & 1)) * ASTG;

        #pragma unroll
        for (int ks = 0; ks < 4; ks++) {
            uint32_t af[4][4];
            #pragma unroll
            for (int mf = 0; mf < 4; mf++) {
                int rb = wm * 64 + mf * 16;
                af[mf][0] = f2tf(__uint_as_float(Asb[(rb + g    ) * 36 + ks * 8 + t    ]));
                af[mf][1] = f2tf(__uint_as_float(Asb[(rb + g + 8) * 36 + ks * 8 + t    ]));
                af[mf][2] = f2tf(__uint_as_float(Asb[(rb + g    ) * 36 + ks * 8 + t + 4]));
                af[mf][3] = f2tf(__uint_as_float(Asb[(rb + g + 8) * 36 + ks * 8 + t + 4]));
            }
            #pragma unroll
            for (int nf = 0; nf < 4; nf++) {
                int nb = wn * 32 + nf * 8;
                uint32_t bf[2];
                bf[0] = Bsb[(nb + g) * 36 + ks * 8 + t];
                bf[1] = Bsb[(nb + g) * 36 + ks * 8 + t + 4];
                #pragma unroll
                for (int mf = 0; mf < 4; mf++)
                    mma_tf32(acc[mf][nf], af[mf], bf);
            }
        }
        __syncthreads();
    }

    #pragma unroll
    for (int mf = 0; mf < 4; mf++) {
        int r0 = m0 + wm * 64 + mf * 16 + g;
        #pragma unroll
        for (int nf = 0; nf < 4; nf++) {
            int cc = n0 + wn * 32 + nf * 8 + 2 * t;
            float b0 = 0.f, b1 = 0.f;
            if (bias) { b0 = __ldg(&bias[cc]); b1 = __ldg(&bias[cc + 1]); }
            float2 v0 = { acc[mf][nf][0] + b0, acc[mf][nf][1] + b1 };
            float2 v1 = { acc[mf][nf][2] + b0, acc[mf][nf][3] + b1 };
            *(float2*)(C + (size_t)r0 * ldc + cc)       = v0;
            *(float2*)(C + (size_t)(r0 + 8) * ldc + cc) = v1;
        }
    }
}

// ============================================================
// 4a) local window attention (tf32 mma), 128 threads, 1 window
// ============================================================
#define AS_STR 68
#define ATTL_SMEM (3 * 64 * AS_STR * 4)

__global__ __launch_bounds__(128)
void attn_local_kernel(const float* __restrict__ Q, const float* __restrict__ KV,
                       float* __restrict__ wfacc) {
    extern __shared__ uint32_t smu[];
    uint32_t* Ks = smu;
    uint32_t* Vs = Ks + 64 * AS_STR;
    uint32_t* Ps = Vs + 64 * AS_STR;

    int n = blockIdx.x, h = blockIdx.y;
    int tid = threadIdx.x;
    int lane = tid & 31, w = tid >> 5;
    int g = lane >> 2, t = lane & 3;
    int qtok0 = n * WINSZ;
    int qrow0 = w * 16;

    uint32_t qf[8][4];
    {
        const float* qb = Q + (size_t)(qtok0 + qrow0) * Cn + h * CH;
        #pragma unroll
        for (int ks = 0; ks < 8; ks++) {
            qf[ks][0] = f2tf(qb[(size_t)(g    ) * Cn + ks * 8 + t    ] * SCALE);
            qf[ks][1] = f2tf(qb[(size_t)(g + 8) * Cn + ks * 8 + t    ] * SCALE);
            qf[ks][2] = f2tf(qb[(size_t)(g    ) * Cn + ks * 8 + t + 4] * SCALE);
            qf[ks][3] = f2tf(qb[(size_t)(g + 8) * Cn + ks * 8 + t + 4] * SCALE);
        }
    }

    for (int i = tid; i < 1024; i += 128) {
        int tok = i >> 4, c4 = (i & 15) << 2;
        const float* base = KV + (size_t)(qtok0 + tok) * (2 * Cn) + h * CH;
        float4 kv4 = *(const float4*)(base + c4);
        float4 vv4 = *(const float4*)(base + Cn + c4);
        uint4 kk = { f2tf(kv4.x), f2tf(kv4.y), f2tf(kv4.z), f2tf(kv4.w) };
        uint4 vv = { f2tf(vv4.x), f2tf(vv4.y), f2tf(vv4.z), f2tf(vv4.w) };
        *(uint4*)(Ks + tok * AS_STR + c4) = kk;
        *(uint4*)(Vs + tok * AS_STR + c4) = vv;
    }
    __syncthreads();

    float ss[8][4] = {};
    #pragma unroll
    for (int nf = 0; nf < 8; nf++) {
        #pragma unroll
        for (int ks = 0; ks < 8; ks++) {
            uint32_t bf[2];
            bf[0] = Ks[(nf * 8 + g) * AS_STR + ks * 8 + t];
            bf[1] = Ks[(nf * 8 + g) * AS_STR + ks * 8 + t + 4];
            mma_tf32(ss[nf], qf[ks], bf);
        }
    }

    float cm0 = -1e30f, cm1 = -1e30f;
    #pragma unroll
    for (int nf = 0; nf < 8; nf++) {
        cm0 = fmaxf(cm0, fmaxf(ss[nf][0], ss[nf][1]));
        cm1 = fmaxf(cm1, fmaxf(ss[nf][2], ss[nf][3]));
    }
    cm0 = fmaxf(cm0, __shfl_xor_sync(0xffffffffu, cm0, 1));
    cm0 = fmaxf(cm0, __shfl_xor_sync(0xffffffffu, cm0, 2));
    cm1 = fmaxf(cm1, __shfl_xor_sync(0xffffffffu, cm1, 1));
    cm1 = fmaxf(cm1, __shfl_xor_sync(0xffffffffu, cm1, 2));
    float sum0 = 0.f, sum1 = 0.f;
    #pragma unroll
    for (int nf = 0; nf < 8; nf++) {
        ss[nf][0] = __expf(ss[nf][0] - cm0);
        ss[nf][1] = __expf(ss[nf][1] - cm0);
        ss[nf][2] = __expf(ss[nf][2] - cm1);
        ss[nf][3] = __expf(ss[nf][3] - cm1);
        sum0 += ss[nf][0] + ss[nf][1];
        sum1 += ss[nf][2] + ss[nf][3];
    }
    sum0 += __shfl_xor_sync(0xffffffffu, sum0, 1);
    sum0 += __shfl_xor_sync(0xffffffffu, sum0, 2);
    sum1 += __shfl_xor_sync(0xffffffffu, sum1, 1);
    sum1 += __shfl_xor_sync(0xffffffffu, sum1, 2);

    #pragma unroll
    for (int nf = 0; nf < 8; nf++) {
        int pc = nf * 8 + 2 * t;
        uint2 p0 = { f2tf(ss[nf][0]), f2tf(ss[nf][1]) };
        uint2 p1 = { f2tf(ss[nf][2]), f2tf(ss[nf][3]) };
        *(uint2*)(Ps + (qrow0 + g) * AS_STR + pc)     = p0;
        *(uint2*)(Ps + (qrow0 + g + 8) * AS_STR + pc) = p1;
    }
    __syncwarp();

    float of[8][4] = {};
    #pragma unroll
    for (int ks2 = 0; ks2 < 8; ks2++) {
        uint32_t pa[4];
        pa[0] = Ps[(qrow0 + g    ) * AS_STR + ks2 * 8 + t];
        pa[1] = Ps[(qrow0 + g + 8) * AS_STR + ks2 * 8 + t];
        pa[2] = Ps[(qrow0 + g    ) * AS_STR + ks2 * 8 + t + 4];
        pa[3] = Ps[(qrow0 + g + 8) * AS_STR + ks2 * 8 + t + 4];
        #pragma unroll
        for (int nf2 = 0; nf2 < 8; nf2++) {
            uint32_t bf[2];
            bf[0] = Vs[(ks2 * 8 + t    ) * AS_STR + nf2 * 8 + g];
            bf[1] = Vs[(ks2 * 8 + t + 4) * AS_STR + nf2 * 8 + g];
            mma_tf32(of[nf2], pa, bf);
        }
    }

    float inv0 = 1.f / sum0, inv1 = 1.f / sum1;
    #pragma unroll
    for (int nf = 0; nf < 8; nf++) {
        float* p0 = wfacc + (size_t)(qtok0 + qrow0 + g) * Cn + h * CH + nf * 8 + 2 * t;
        float* p1 = wfacc + (size_t)(qtok0 + qrow0 + g + 8) * Cn + h * CH + nf * 8 + 2 * t;
        float2 o0 = *(float2*)p0;
        float2 o1 = *(float2*)p1;
        o0.x += of[nf][0] * inv0; o0.y += of[nf][1] * inv0;
        o1.x += of[nf][2] * inv1; o1.y += of[nf][3] * inv1;
        *(float2*)p0 = o0;
        *(float2*)p1 = o1;
    }
}

// ============================================================
// 4b) global cross-attention: 2 windows / block, 256 threads
// ============================================================
#define ATTG_SMEM ((64 + 64 + 128) * AS_STR * 4)

__global__ __launch_bounds__(256)
void attn_global_kernel(const float* __restrict__ Q, const float* __restrict__ KV,
                        float* __restrict__ wfacc) {
    extern __shared__ uint32_t smu[];
    uint32_t* Ks = smu;
    uint32_t* Vs = Ks + 64 * AS_STR;
    uint32_t* Ps = Vs + 64 * AS_STR;

    int b = blockIdx.x / PPB, pb = blockIdx.x % PPB;
    int h = blockIdx.y;
    int s0 = b * NWF + pb * 2;
    bool has2 = (pb * 2 + 1) < NWF;

    int tid = threadIdx.x;
    int lane = tid & 31, w = tid >> 5;
    int g = lane >> 2, t = lane & 3;
    int qrow0 = w * 16;
    int myslot = (qrow0 < 64) ? s0 : (has2 ? s0 + 1 : s0);
    bool wb = (qrow0 < 64) || has2;
    int qtok0 = myslot * WINSZ + (qrow0 & 63);
    int kbase = b * HW1;

    uint32_t qf[8][4];
    {
        const float* qb = Q + (size_t)qtok0 * Cn + h * CH;
        #pragma unroll
        for (int ks = 0; ks < 8; ks++) {
            qf[ks][0] = f2tf(qb[(size_t)(g    ) * Cn + ks * 8 + t    ] * SCALE);
            qf[ks][1] = f2tf(qb[(size_t)(g + 8) * Cn + ks * 8 + t    ] * SCALE);
            qf[ks][2] = f2tf(qb[(size_t)(g    ) * Cn + ks * 8 + t + 4] * SCALE);
            qf[ks][3] = f2tf(qb[(size_t)(g + 8) * Cn + ks * 8 + t + 4] * SCALE);
        }
    }

    float of[8][4] = {};
    float rm0 = -1e30f, rm1 = -1e30f, rl0 = 0.f, rl1 = 0.f;

    for (int chk = 0; chk < 16; chk++) {
        __syncthreads();
        for (int i = tid; i < 1024; i += 256) {
            int tok = i >> 4, c4 = (i & 15) << 2;
            const float* base = KV + (size_t)(kbase + chk * 64 + tok) * (2 * Cn) + h * CH;
            float4 kv4 = *(const float4*)(base + c4);
            float4 vv4 = *(const float4*)(base + Cn + c4);
            uint4 kk = { f2tf(kv4.x), f2tf(kv4.y), f2tf(kv4.z), f2tf(kv4.w) };
            uint4 vv = { f2tf(vv4.x), f2tf(vv4.y), f2tf(vv4.z), f2tf(vv4.w) };
            *(uint4*)(Ks + tok * AS_STR + c4) = kk;
            *(uint4*)(Vs + tok * AS_STR + c4) = vv;
        }
        __syncthreads();

        float ss[8][4] = {};
        #pragma unroll
        for (int nf = 0; nf < 8; nf++) {
            #pragma unroll
            for (int ks = 0; ks < 8; ks++) {
                uint32_t bf[2];
                bf[0] = Ks[(nf * 8 + g) * AS_STR + ks * 8 + t];
                bf[1] = Ks[(nf * 8 + g) * AS_STR + ks * 8 + t + 4];
                mma_tf32(ss[nf], qf[ks], bf);
            }
        }

        float cm0 = -1e30f, cm1 = -1e30f;
        #pragma unroll
        for (int nf = 0; nf < 8; nf++) {
            cm0 = fmaxf(cm0, fmaxf(ss[nf][0], ss[nf][1]));
            cm1 = fmaxf(cm1, fmaxf(ss[nf][2], ss[nf][3]));
        }
        cm0 = fmaxf(cm0, __shfl_xor_sync(0xffffffffu, cm0, 1));
        cm0 = fmaxf(cm0, __shfl_xor_sync(0xffffffffu, cm0, 2));
        cm1 = fmaxf(cm1, __shfl_xor_sync(0xffffffffu, cm1, 1));
        cm1 = fmaxf(cm1, __shfl_xor_sync(0xffffffffu, cm1, 2));
        float nm0 = fmaxf(rm0, cm0), nm1 = fmaxf(rm1, cm1);
        float scl0 = __expf(rm0 - nm0), scl1 = __expf(rm1 - nm1);
        float sum0 = 0.f, sum1 = 0.f;
        #pragma unroll
        for (int nf = 0; nf < 8; nf++) {
            ss[nf][0] = __expf(ss[nf][0] - nm0);
            ss[nf][1] = __expf(ss[nf][1] - nm0);
            ss[nf][2] = __expf(ss[nf][2] - nm1);
            ss[nf][3] = __expf(ss[nf][3] - nm1);
            sum0 += ss[nf][0] + ss[nf][1];
            sum1 += ss[nf][2] + ss[nf][3];
        }
        sum0 += __shfl_xor_sync(0xffffffffu, sum0, 1);
        sum0 += __shfl_xor_sync(0xffffffffu, sum0, 2);
        sum1 += __shfl_xor_sync(0xffffffffu, sum1, 1);
        sum1 += __shfl_xor_sync(0xffffffffu, sum1, 2);
        rl0 = rl0 * scl0 + sum0;  rm0 = nm0;
        rl1 = rl1 * scl1 + sum1;  rm1 = nm1;
        #pragma unroll
        for (int nf = 0; nf < 8; nf++) {
            of[nf][0] *= scl0; of[nf][1] *= scl0;
            of[nf][2] *= scl1; of[nf][3] *= scl1;
        }

        #pragma unroll
        for (int nf = 0; nf < 8; nf++) {
            int pc = nf * 8 + 2 * t;
            uint2 p0 = { f2tf(ss[nf][0]), f2tf(ss[nf][1]) };
            uint2 p1 = { f2tf(ss[nf][2]), f2tf(ss[nf][3]) };
            *(uint2*)(Ps + (qrow0 + g) * AS_STR + pc)     = p0;
            *(uint2*)(Ps + (qrow0 + g + 8) * AS_STR + pc) = p1;
        }
        __syncwarp();

        #pragma unroll
        for (int ks2 = 0; ks2 < 8; ks2++) {
            uint32_t pa[4];
            pa[0] = Ps[(qrow0 + g    ) * AS_STR + ks2 * 8 + t];
            pa[1] = Ps[(qrow0 + g + 8) * AS_STR + ks2 * 8 + t];
            pa[2] = Ps[(qrow0 + g    ) * AS_STR + ks2 * 8 + t + 4];
            pa[3] = Ps[(qrow0 + g + 8) * AS_STR + ks2 * 8 + t + 4];
            #pragma unroll
            for (int nf2 = 0; nf2 < 8; nf2++) {
                uint32_t bf[2];
                bf[0] = Vs[(ks2 * 8 + t    ) * AS_STR + nf2 * 8 + g];
                bf[1] = Vs[(ks2 * 8 + t + 4) * AS_STR + nf2 * 8 + g];
                mma_tf32(of[nf2], pa, bf);
            }
        }
        __syncwarp();
    }

    if (wb) {
        float inv0 = 1.f / rl0, inv1 = 1.f / rl1;
        #pragma unroll
        for (int nf = 0; nf < 8; nf++) {
            float* p0 = wfacc + (size_t)(qtok0 + g) * Cn + h * CH + nf * 8 + 2 * t;
            float* p1 = wfacc + (size_t)(qtok0 + g + 8) * Cn + h * CH + nf * 8 + 2 * t;
            float2 o0 = *(float2*)p0;
            float2 o1 = *(float2*)p1;
            o0.x += of[nf][0] * inv0; o0.y += of[nf][1] * inv0;
            o1.x += of[nf][2] * inv1; o1.y += of[nf][3] * inv1;
            *(float2*)p0 = o0;
            *(float2*)p1 = o1;
        }
    }
}

// ============================================================
// 5) global branch: depthwise conv -> LN -> exact GELU
// ============================================================
__global__ void convlngelu_kernel(const float* __restrict__ feat,
                                  const float* __restrict__ sr_w,
                                  const float* __restrict__ sr_b,
                                  const float* __restrict__ ln_g,
                                  const float* __restrict__ ln_b,
                                  float* __restrict__ g) {
    __shared__ float red[Cn];
    int bt = blockIdx.x;
    int b = bt >> 10, t = bt & 1023;
    int y1 = t >> 5, x1 = t & 31;
    int c = threadIdx.x;

    const float* src = feat + (((size_t)b * Cn + c) * Hn + y1 * SRn) * Wn + x1 * SRn;
    const float* w = sr_w + c * (SRn * SRn);
    float acc = sr_b[c];
    #pragma unroll
    for (int i = 0; i < SRn; i++)
        #pragma unroll
        for (int j = 0; j < SRn; j++)
            acc += src[i * Wn + j] * w[i * SRn + j];

    red[c] = acc;
    __syncthreads();
    for (int off = 128; off > 0; off >>= 1) {
        if (c < off) red[c] += red[c + off];
        __syncthreads();
    }
    float mu = red[0] * (1.f / Cn);
    __syncthreads();
    float dv = acc - mu;
    red[c] = dv * dv;
    __syncthreads();
    for (int off = 128; off > 0; off >>= 1) {
        if (c < off) red[c] += red[c + off];
        __syncthreads();
    }
    float var = red[0] * (1.f / Cn);
    float rs = rsqrtf(var + 1e-5f);
    float xh = dv * rs * ln_g[c] + ln_b[c];
    float gl = 0.5f * xh * (1.f + erff(xh * 0.70710678118654752440f));
    g[(size_t)bt * Cn + c] = gl;
}

// ============================================================
// 6) scatter-add projected windows back into out
// ============================================================
__global__ void scatter_kernel(const float* __restrict__ P, const int* __restrict__ sel,
                               float* __restrict__ out) {
    int n = blockIdx.x;
    int c = threadIdx.x;
    int b = n / NWF;
    int wi = sel[n];
    int wh = wi >> 5, ww = wi & 31;
    const float* src = P + (size_t)n * WINSZ * Cn + c;
    float* dst = out + (((size_t)b * Cn + c) * Hn + wh * WSZ) * Wn + ww * WSZ;
    #pragma unroll
    for (int p = 0; p < WINSZ; p++)
        dst[(p >> 3) * Wn + (p & 7)] += src[p * Cn];
}

// ============================================================
// launch
// ============================================================
extern "C" void kernel_launch(void* const* d_in, const int* in_sizes, int n_in,
                              void* d_out, int out_size) {
    const float* feat  = (const float*)d_in[0];
    const float* unc   = (const float*)d_in[1];
    const float* sr_w  = (const float*)d_in[2];
    const float* sr_b  = (const float*)d_in[3];
    const float* ln_g  = (const float*)d_in[4];
    const float* ln_b  = (const float*)d_in[5];
    const float* wq_l  = (const float*)d_in[6];
    const float* wkv_l = (const float*)d_in[7];
    const float* wq_g  = (const float*)d_in[8];
    const float* wkv_g = (const float*)d_in[9];
    const float* wp    = (const float*)d_in[10];
    const float* bp    = (const float*)d_in[11];
    float* out = (float*)d_out;

    float *wf, *q, *kv, *g;
    uint32_t *wtql, *wtkvl, *wtqg, *wtkvg, *wtp;
    int* sel;
    cudaGetSymbolAddress((void**)&wf,    d_wf);
    cudaGetSymbolAddress((void**)&q,     d_q);
    cudaGetSymbolAddress((void**)&kv,    d_kv);
    cudaGetSymbolAddress((void**)&g,     d_g);
    cudaGetSymbolAddress((void**)&sel,   d_sel);
    cudaGetSymbolAddress((void**)&wtql,  d_wtql);
    cudaGetSymbolAddress((void**)&wtkvl, d_wtkvl);
    cudaGetSymbolAddress((void**)&wtqg,  d_wtqg);
    cudaGetSymbolAddress((void**)&wtkvg, d_wtkvg);
    cudaGetSymbolAddress((void**)&wtp,   d_wtp);

    cudaFuncSetAttribute(mma_gemm_kernel, cudaFuncAttributeMaxDynamicSharedMemorySize, GEMM_SMEM);
    cudaFuncSetAttribute(attn_local_kernel, cudaFuncAttributeMaxDynamicSharedMemorySize, ATTL_SMEM);
    cudaFuncSetAttribute(attn_global_kernel, cudaFuncAttributeMaxDynamicSharedMemorySize, ATTG_SMEM);

    cudaMemcpyAsync(out, feat, (size_t)Bn * Cn * Hn * Wn * sizeof(float),
                    cudaMemcpyDeviceToDevice);

    transpose_all_kernel<<<dim3(8, 16, 5), dim3(32, 8)>>>(
        wq_l, wkv_l, wq_g, wkv_g, wp, wtql, wtkvl, wtqg, wtkvg, wtp);

    select_kernel<<<Bn, NWIN>>>(unc, sel);
    gather_kernel<<<NSEL, Cn>>>(feat, sel, wf);

    // local branch
    mma_gemm_kernel<<<dim3(NTOK / 128, 2), 256, GEMM_SMEM>>>(wf, wtql, q, nullptr, Cn);
    mma_gemm_kernel<<<dim3(NTOK / 128, 4), 256, GEMM_SMEM>>>(wf, wtkvl, kv, nullptr, 2 * Cn);
    attn_local_kernel<<<dim3(NSEL, HEADS), 128, ATTL_SMEM>>>(q, kv, wf);

    // global branch
    convlngelu_kernel<<<GTOK, Cn>>>(feat, sr_w, sr_b, ln_g, ln_b, g);
    mma_gemm_kernel<<<dim3(GTOK / 128, 4), 256, GEMM_SMEM>>>(g, wtkvg, kv, nullptr, 2 * Cn);

    mma_gemm_kernel<<<dim3(NTOK / 128, 2), 256, GEMM_SMEM>>>(wf, wtqg, q, nullptr, Cn);
    attn_global_kernel<<<dim3(Bn * PPB, HEADS), 256, ATTG_SMEM>>>(q, kv, wf);

    // projection + scatter
    mma_gemm_kernel<<<dim3(NTOK / 128, 2), 256, GEMM_SMEM>>>(wf, wtp, q, bp, Cn);
    scatter_kernel<<<NSEL, Cn>>>(q, sel, out);
}

// round 8
// speedup vs baseline: 1.2077x; 1.0026x over previous
#include <cuda_runtime.h>
#include <cuda_bf16.h>
#include <math.h>
#include <stdint.h>

// ---------------- problem constants ----------------
#define Bn      2
#define Cn      256
#define Hn      256
#define Wn      256
#define HEADS   4
#define CH      64
#define WSZ     8
#define NH      32
#define NWIN    1024
#define WINSZ   64
#define NWF     307
#define NSEL    614
#define SRn     8
#define H1      32
#define HW1     1024
#define NTOK    (NSEL*WINSZ)   // 39296
#define GTOK    (Bn*HW1)       // 2048
#define SCALE   0.125f
#define GK      256
#define PPB     154

// ---------------- scratch ----------------
__device__ float d_wf[NTOK * Cn];
__device__ float d_q [NTOK * Cn];
__device__ float d_kv[NTOK * 2 * Cn];
__device__ float d_g [GTOK * Cn];
__device__ int   d_sel[NSEL];
__device__ uint32_t d_wtql [Cn * Cn];      // tf32 bits, [n][k]
__device__ uint32_t d_wtkvl[2 * Cn * Cn];
__device__ uint32_t d_wtqg [Cn * Cn];
__device__ uint32_t d_wtkvg[2 * Cn * Cn];
__device__ uint32_t d_wtp  [Cn * Cn];

// ---------------- helpers ----------------
__device__ __forceinline__ uint32_t f2tf(float x) {
    uint32_t r;
    asm("cvt.rna.tf32.f32 %0, %1;" : "=r"(r) : "f"(x));
    return r;
}
__device__ __forceinline__ void mma_tf32(float d[4], const uint32_t a[4], const uint32_t b[2]) {
    asm volatile(
        "mma.sync.aligned.m16n8k8.row.col.f32.tf32.tf32.f32 "
        "{%0,%1,%2,%3}, {%4,%5,%6,%7}, {%8,%9}, {%0,%1,%2,%3};"
        : "+f"(d[0]), "+f"(d[1]), "+f"(d[2]), "+f"(d[3])
        : "r"(a[0]), "r"(a[1]), "r"(a[2]), "r"(a[3]), "r"(b[0]), "r"(b[1]));
}
__device__ __forceinline__ uint32_t smem_u32(const void* p) {
    uint32_t a;
    asm("{ .reg .u64 t; cvta.to.shared.u64 t, %1; cvt.u32.u64 %0, t; }" : "=r"(a) : "l"(p));
    return a;
}
__device__ __forceinline__ void cp_async16(uint32_t saddr, const void* g) {
    asm volatile("cp.async.cg.shared.global [%0], [%1], 16;" :: "r"(saddr), "l"(g));
}
#define CP_COMMIT() asm volatile("cp.async.commit_group;" ::: "memory")
#define CP_WAIT0()  asm volatile("cp.async.wait_group 0;" ::: "memory")
#define CP_WAIT1()  asm volatile("cp.async.wait_group 1;" ::: "memory")

// ============================================================
// 0) weight transpose + tf32 pre-round: WT[n][k] = tf32(W[k][n])
// ============================================================
__global__ void transpose_all_kernel(
    const float* __restrict__ w0, const float* __restrict__ w1,
    const float* __restrict__ w2, const float* __restrict__ w3,
    const float* __restrict__ w4,
    uint32_t* __restrict__ t0, uint32_t* __restrict__ t1,
    uint32_t* __restrict__ t2, uint32_t* __restrict__ t3,
    uint32_t* __restrict__ t4) {
    __shared__ float t[32][33];
    const float* W; uint32_t* WT; int N;
    switch (blockIdx.z) {
        case 0:  W = w0; WT = t0; N = Cn;     break;
        case 1:  W = w1; WT = t1; N = 2 * Cn; break;
        case 2:  W = w2; WT = t2; N = Cn;     break;
        case 3:  W = w3; WT = t3; N = 2 * Cn; break;
        default: W = w4; WT = t4; N = Cn;     break;
    }
    int kx = blockIdx.x * 32, nx = blockIdx.y * 32;
    if (nx >= N) return;
    for (int r = threadIdx.y; r < 32; r += 8)
        t[r][threadIdx.x] = W[(size_t)(kx + r) * N + nx + threadIdx.x];
    __syncthreads();
    for (int r = threadIdx.y; r < 32; r += 8)
        WT[(size_t)(nx + r) * GK + kx + threadIdx.x] = f2tf(t[threadIdx.x][r]);
}

// ============================================================
// 1) top-k window selection
// ============================================================
__global__ void select_kernel(const float* __restrict__ unc, int* __restrict__ sel) {
    __shared__ float sc[NWIN];
    int b  = blockIdx.x;
    int wi = threadIdx.x;
    int wh = wi >> 5, ww = wi & 31;
    const float* u = unc + ((size_t)b * Hn + wh * WSZ) * Wn + ww * WSZ;
    float s = 0.f;
    #pragma unroll
    for (int i = 0; i < WSZ; i++)
        #pragma unroll
        for (int j = 0; j < WSZ; j++)
            s += u[i * Wn + j];
    sc[wi] = s;
    __syncthreads();
    int rank = 0;
    for (int j = 0; j < NWIN; j++) {
        float sj = sc[j];
        rank += (sj > s) || (sj == s && j < wi);
    }
    if (rank < NWF) sel[b * NWF + rank] = wi;
}

// ============================================================
// 2) gather selected windows
// ============================================================
__global__ void gather_kernel(const float* __restrict__ feat, const int* __restrict__ sel,
                              float* __restrict__ wf) {
    int n = blockIdx.x;
    int c = threadIdx.x;
    int b = n / NWF;
    int wi = sel[n];
    int wh = wi >> 5, ww = wi & 31;
    const float* src = feat + (((size_t)b * Cn + c) * Hn + wh * WSZ) * Wn + ww * WSZ;
    float* dst = wf + (size_t)n * WINSZ * Cn + c;
    #pragma unroll
    for (int p = 0; p < WINSZ; p++)
        dst[p * Cn] = src[(p >> 3) * Wn + (p & 7)];
}

// ============================================================
// 3) tf32 mma.sync GEMM, 128x128 tile, BK=32, cp.async 2-stage
//    8 warps = 2m x 4n; warp = 64x32 = 4x4 fragments
// ============================================================
#define ASTG (128 * 36)
#define GEMM_SMEM (4 * ASTG * 4)   // 73728 bytes

__global__ __launch_bounds__(256)
void mma_gemm_kernel(const float* __restrict__ A, const uint32_t* __restrict__ WT,
                     float* __restrict__ C, const float* __restrict__ bias, int ldc) {
    extern __shared__ uint32_t sg[];
    int tid = threadIdx.x;
    int lane = tid & 31, wid = tid >> 5;
    int g = lane >> 2, t = lane & 3;
    int wm = wid & 1, wn = wid >> 1;
    int m0 = blockIdx.x * 128, n0 = blockIdx.y * 128;

    uint32_t sbase = smem_u32(sg);

    // chunk coords for this thread (4 chunks of 16B each for A and B per stage)
    int crow[4], cq4[4];
    #pragma unroll
    for (int u = 0; u < 4; u++) {
        int c = tid + u * 256;
        crow[u] = c >> 3;
        cq4[u]  = (c & 7) << 2;
    }

    // stage loader
    auto load_stage = [&](int kc, int buf) {
        uint32_t a_s = sbase + (uint32_t)(buf * ASTG) * 4u;
        uint32_t b_s = sbase + (uint32_t)((2 + buf) * ASTG) * 4u;
        #pragma unroll
        for (int u = 0; u < 4; u++) {
            int row = crow[u], q4 = cq4[u];
            cp_async16(a_s + (uint32_t)(row * 36 + q4) * 4u,
                       A + (size_t)(m0 + row) * GK + kc + q4);
            cp_async16(b_s + (uint32_t)(row * 36 + q4) * 4u,
                       WT + (size_t)(n0 + row) * GK + kc + q4);
        }
    };

    float acc[4][4][4] = {};

    load_stage(0, 0);
    CP_COMMIT();

    #pragma unroll 1
    for (int st = 0; st < 8; st++) {
        if (st < 7) {
            load_stage((st + 1) * 32, (st + 1) & 1);
            CP_COMMIT();
            CP_WAIT1();
        } else {
            CP_WAIT0();
        }
        __syncthreads();

        const uint32_t* Asb = sg + (st & 1) * ASTG;
        const uint32_t* Bsb = sg + (2 + (st & 1)) * ASTG;

        #pragma unroll
        for (int ks = 0; ks < 4; ks++) {
            uint32_t af[4][4];
            #pragma unroll
            for (int mf = 0; mf < 4; mf++) {
                int rb = wm * 64 + mf * 16;
                af[mf][0] = f2tf(__uint_as_float(Asb[(rb + g    ) * 36 + ks * 8 + t    ]));
                af[mf][1] = f2tf(__uint_as_float(Asb[(rb + g + 8) * 36 + ks * 8 + t    ]));
                af[mf][2] = f2tf(__uint_as_float(Asb[(rb + g    ) * 36 + ks * 8 + t + 4]));
                af[mf][3] = f2tf(__uint_as_float(Asb[(rb + g + 8) * 36 + ks * 8 + t + 4]));
            }
            #pragma unroll
            for (int nf = 0; nf < 4; nf++) {
                int nb = wn * 32 + nf * 8;
                uint32_t bf[2];
                bf[0] = Bsb[(nb + g) * 36 + ks * 8 + t];
                bf[1] = Bsb[(nb + g) * 36 + ks * 8 + t + 4];
                #pragma unroll
                for (int mf = 0; mf < 4; mf++)
                    mma_tf32(acc[mf][nf], af[mf], bf);
            }
        }
        __syncthreads();
    }

    #pragma unroll
    for (int mf = 0; mf < 4; mf++) {
        int r0 = m0 + wm * 64 + mf * 16 + g;
        #pragma unroll
        for (int nf = 0; nf < 4; nf++) {
            int cc = n0 + wn * 32 + nf * 8 + 2 * t;
            float b0 = 0.f, b1 = 0.f;
            if (bias) { b0 = __ldg(&bias[cc]); b1 = __ldg(&bias[cc + 1]); }
            float2 v0 = { acc[mf][nf][0] + b0, acc[mf][nf][1] + b1 };
            float2 v1 = { acc[mf][nf][2] + b0, acc[mf][nf][3] + b1 };
            *(float2*)(C + (size_t)r0 * ldc + cc)       = v0;
            *(float2*)(C + (size_t)(r0 + 8) * ldc + cc) = v1;
        }
    }
}

// ============================================================
// 4a) local window attention (tf32 mma), 128 threads, 1 window
// ============================================================
#define AS_STR 68
#define ATTL_SMEM (3 * 64 * AS_STR * 4)

__global__ __launch_bounds__(128)
void attn_local_kernel(const float* __restrict__ Q, const float* __restrict__ KV,
                       float* __restrict__ wfacc) {
    extern __shared__ uint32_t smu[];
    uint32_t* Ks = smu;
    uint32_t* Vs = Ks + 64 * AS_STR;
    uint32_t* Ps = Vs + 64 * AS_STR;

    int n = blockIdx.x, h = blockIdx.y;
    int tid = threadIdx.x;
    int lane = tid & 31, w = tid >> 5;
    int g = lane >> 2, t = lane & 3;
    int qtok0 = n * WINSZ;
    int qrow0 = w * 16;

    uint32_t qf[8][4];
    {
        const float* qb = Q + (size_t)(qtok0 + qrow0) * Cn + h * CH;
        #pragma unroll
        for (int ks = 0; ks < 8; ks++) {
            qf[ks][0] = f2tf(qb[(size_t)(g    ) * Cn + ks * 8 + t    ] * SCALE);
            qf[ks][1] = f2tf(qb[(size_t)(g + 8) * Cn + ks * 8 + t    ] * SCALE);
            qf[ks][2] = f2tf(qb[(size_t)(g    ) * Cn + ks * 8 + t + 4] * SCALE);
            qf[ks][3] = f2tf(qb[(size_t)(g + 8) * Cn + ks * 8 + t + 4] * SCALE);
        }
    }

    for (int i = tid; i < 1024; i += 128) {
        int tok = i >> 4, c4 = (i & 15) << 2;
        const float* base = KV + (size_t)(qtok0 + tok) * (2 * Cn) + h * CH;
        float4 kv4 = *(const float4*)(base + c4);
        float4 vv4 = *(const float4*)(base + Cn + c4);
        uint4 kk = { f2tf(kv4.x), f2tf(kv4.y), f2tf(kv4.z), f2tf(kv4.w) };
        uint4 vv = { f2tf(vv4.x), f2tf(vv4.y), f2tf(vv4.z), f2tf(vv4.w) };
        *(uint4*)(Ks + tok * AS_STR + c4) = kk;
        *(uint4*)(Vs + tok * AS_STR + c4) = vv;
    }
    __syncthreads();

    float ss[8][4] = {};
    #pragma unroll
    for (int nf = 0; nf < 8; nf++) {
        #pragma unroll
        for (int ks = 0; ks < 8; ks++) {
            uint32_t bf[2];
            bf[0] = Ks[(nf * 8 + g) * AS_STR + ks * 8 + t];
            bf[1] = Ks[(nf * 8 + g) * AS_STR + ks * 8 + t + 4];
            mma_tf32(ss[nf], qf[ks], bf);
        }
    }

    float cm0 = -1e30f, cm1 = -1e30f;
    #pragma unroll
    for (int nf = 0; nf < 8; nf++) {
        cm0 = fmaxf(cm0, fmaxf(ss[nf][0], ss[nf][1]));
        cm1 = fmaxf(cm1, fmaxf(ss[nf][2], ss[nf][3]));
    }
    cm0 = fmaxf(cm0, __shfl_xor_sync(0xffffffffu, cm0, 1));
    cm0 = fmaxf(cm0, __shfl_xor_sync(0xffffffffu, cm0, 2));
    cm1 = fmaxf(cm1, __shfl_xor_sync(0xffffffffu, cm1, 1));
    cm1 = fmaxf(cm1, __shfl_xor_sync(0xffffffffu, cm1, 2));
    float sum0 = 0.f, sum1 = 0.f;
    #pragma unroll
    for (int nf = 0; nf < 8; nf++) {
        ss[nf][0] = __expf(ss[nf][0] - cm0);
        ss[nf][1] = __expf(ss[nf][1] - cm0);
        ss[nf][2] = __expf(ss[nf][2] - cm1);
        ss[nf][3] = __expf(ss[nf][3] - cm1);
        sum0 += ss[nf][0] + ss[nf][1];
        sum1 += ss[nf][2] + ss[nf][3];
    }
    sum0 += __shfl_xor_sync(0xffffffffu, sum0, 1);
    sum0 += __shfl_xor_sync(0xffffffffu, sum0, 2);
    sum1 += __shfl_xor_sync(0xffffffffu, sum1, 1);
    sum1 += __shfl_xor_sync(0xffffffffu, sum1, 2);

    #pragma unroll
    for (int nf = 0; nf < 8; nf++) {
        int pc = nf * 8 + 2 * t;
        uint2 p0 = { f2tf(ss[nf][0]), f2tf(ss[nf][1]) };
        uint2 p1 = { f2tf(ss[nf][2]), f2tf(ss[nf][3]) };
        *(uint2*)(Ps + (qrow0 + g) * AS_STR + pc)     = p0;
        *(uint2*)(Ps + (qrow0 + g + 8) * AS_STR + pc) = p1;
    }
    __syncwarp();

    float of[8][4] = {};
    #pragma unroll
    for (int ks2 = 0; ks2 < 8; ks2++) {
        uint32_t pa[4];
        pa[0] = Ps[(qrow0 + g    ) * AS_STR + ks2 * 8 + t];
        pa[1] = Ps[(qrow0 + g + 8) * AS_STR + ks2 * 8 + t];
        pa[2] = Ps[(qrow0 + g    ) * AS_STR + ks2 * 8 + t + 4];
        pa[3] = Ps[(qrow0 + g + 8) * AS_STR + ks2 * 8 + t + 4];
        #pragma unroll
        for (int nf2 = 0; nf2 < 8; nf2++) {
            uint32_t bf[2];
            bf[0] = Vs[(ks2 * 8 + t    ) * AS_STR + nf2 * 8 + g];
            bf[1] = Vs[(ks2 * 8 + t + 4) * AS_STR + nf2 * 8 + g];
            mma_tf32(of[nf2], pa, bf);
        }
    }

    float inv0 = 1.f / sum0, inv1 = 1.f / sum1;
    #pragma unroll
    for (int nf = 0; nf < 8; nf++) {
        float* p0 = wfacc + (size_t)(qtok0 + qrow0 + g) * Cn + h * CH + nf * 8 + 2 * t;
        float* p1 = wfacc + (size_t)(qtok0 + qrow0 + g + 8) * Cn + h * CH + nf * 8 + 2 * t;
        float2 o0 = *(float2*)p0;
        float2 o1 = *(float2*)p1;
        o0.x += of[nf][0] * inv0; o0.y += of[nf][1] * inv0;
        o1.x += of[nf][2] * inv1; o1.y += of[nf][3] * inv1;
        *(float2*)p0 = o0;
        *(float2*)p1 = o1;
    }
}

// ============================================================
// 4b) global cross-attention: 2 windows / block, 256 threads
// ============================================================
#define ATTG_SMEM ((64 + 64 + 128) * AS_STR * 4)

__global__ __launch_bounds__(256)
void attn_global_kernel(const float* __restrict__ Q, const float* __restrict__ KV,
                        float* __restrict__ wfacc) {
    extern __shared__ uint32_t smu[];
    uint32_t* Ks = smu;
    uint32_t* Vs = Ks + 64 * AS_STR;
    uint32_t* Ps = Vs + 64 * AS_STR;

    int b = blockIdx.x / PPB, pb = blockIdx.x % PPB;
    int h = blockIdx.y;
    int s0 = b * NWF + pb * 2;
    bool has2 = (pb * 2 + 1) < NWF;

    int tid = threadIdx.x;
    int lane = tid & 31, w = tid >> 5;
    int g = lane >> 2, t = lane & 3;
    int qrow0 = w * 16;
    int myslot = (qrow0 < 64) ? s0 : (has2 ? s0 + 1 : s0);
    bool wb = (qrow0 < 64) || has2;
    int qtok0 = myslot * WINSZ + (qrow0 & 63);
    int kbase = b * HW1;

    uint32_t qf[8][4];
    {
        const float* qb = Q + (size_t)qtok0 * Cn + h * CH;
        #pragma unroll
        for (int ks = 0; ks < 8; ks++) {
            qf[ks][0] = f2tf(qb[(size_t)(g    ) * Cn + ks * 8 + t    ] * SCALE);
            qf[ks][1] = f2tf(qb[(size_t)(g + 8) * Cn + ks * 8 + t    ] * SCALE);
            qf[ks][2] = f2tf(qb[(size_t)(g    ) * Cn + ks * 8 + t + 4] * SCALE);
            qf[ks][3] = f2tf(qb[(size_t)(g + 8) * Cn + ks * 8 + t + 4] * SCALE);
        }
    }

    float of[8][4] = {};
    float rm0 = -1e30f, rm1 = -1e30f, rl0 = 0.f, rl1 = 0.f;

    for (int chk = 0; chk < 16; chk++) {
        __syncthreads();
        for (int i = tid; i < 1024; i += 256) {
            int tok = i >> 4, c4 = (i & 15) << 2;
            const float* base = KV + (size_t)(kbase + chk * 64 + tok) * (2 * Cn) + h * CH;
            float4 kv4 = *(const float4*)(base + c4);
            float4 vv4 = *(const float4*)(base + Cn + c4);
            uint4 kk = { f2tf(kv4.x), f2tf(kv4.y), f2tf(kv4.z), f2tf(kv4.w) };
            uint4 vv = { f2tf(vv4.x), f2tf(vv4.y), f2tf(vv4.z), f2tf(vv4.w) };
            *(uint4*)(Ks + tok * AS_STR + c4) = kk;
            *(uint4*)(Vs + tok * AS_STR + c4) = vv;
        }
        __syncthreads();

        float ss[8][4] = {};
        #pragma unroll
        for (int nf = 0; nf < 8; nf++) {
            #pragma unroll
            for (int ks = 0; ks < 8; ks++) {
                uint32_t bf[2];
                bf[0] = Ks[(nf * 8 + g) * AS_STR + ks * 8 + t];
                bf[1] = Ks[(nf * 8 + g) * AS_STR + ks * 8 + t + 4];
                mma_tf32(ss[nf], qf[ks], bf);
            }
        }

        float cm0 = -1e30f, cm1 = -1e30f;
        #pragma unroll
        for (int nf = 0; nf < 8; nf++) {
            cm0 = fmaxf(cm0, fmaxf(ss[nf][0], ss[nf][1]));
            cm1 = fmaxf(cm1, fmaxf(ss[nf][2], ss[nf][3]));
        }
        cm0 = fmaxf(cm0, __shfl_xor_sync(0xffffffffu, cm0, 1));
        cm0 = fmaxf(cm0, __shfl_xor_sync(0xffffffffu, cm0, 2));
        cm1 = fmaxf(cm1, __shfl_xor_sync(0xffffffffu, cm1, 1));
        cm1 = fmaxf(cm1, __shfl_xor_sync(0xffffffffu, cm1, 2));
        float nm0 = fmaxf(rm0, cm0), nm1 = fmaxf(rm1, cm1);
        float scl0 = __expf(rm0 - nm0), scl1 = __expf(rm1 - nm1);
        float sum0 = 0.f, sum1 = 0.f;
        #pragma unroll
        for (int nf = 0; nf < 8; nf++) {
            ss[nf][0] = __expf(ss[nf][0] - nm0);
            ss[nf][1] = __expf(ss[nf][1] - nm0);
            ss[nf][2] = __expf(ss[nf][2] - nm1);
            ss[nf][3] = __expf(ss[nf][3] - nm1);
            sum0 += ss[nf][0] + ss[nf][1];
            sum1 += ss[nf][2] + ss[nf][3];
        }
        sum0 += __shfl_xor_sync(0xffffffffu, sum0, 1);
        sum0 += __shfl_xor_sync(0xffffffffu, sum0, 2);
        sum1 += __shfl_xor_sync(0xffffffffu, sum1, 1);
        sum1 += __shfl_xor_sync(0xffffffffu, sum1, 2);
        rl0 = rl0 * scl0 + sum0;  rm0 = nm0;
        rl1 = rl1 * scl1 + sum1;  rm1 = nm1;
        #pragma unroll
        for (int nf = 0; nf < 8; nf++) {
            of[nf][0] *= scl0; of[nf][1] *= scl0;
            of[nf][2] *= scl1; of[nf][3] *= scl1;
        }

        #pragma unroll
        for (int nf = 0; nf < 8; nf++) {
            int pc = nf * 8 + 2 * t;
            uint2 p0 = { f2tf(ss[nf][0]), f2tf(ss[nf][1]) };
            uint2 p1 = { f2tf(ss[nf][2]), f2tf(ss[nf][3]) };
            *(uint2*)(Ps + (qrow0 + g) * AS_STR + pc)     = p0;
            *(uint2*)(Ps + (qrow0 + g + 8) * AS_STR + pc) = p1;
        }
        __syncwarp();

        #pragma unroll
        for (int ks2 = 0; ks2 < 8; ks2++) {
            uint32_t pa[4];
            pa[0] = Ps[(qrow0 + g    ) * AS_STR + ks2 * 8 + t];
            pa[1] = Ps[(qrow0 + g + 8) * AS_STR + ks2 * 8 + t];
            pa[2] = Ps[(qrow0 + g    ) * AS_STR + ks2 * 8 + t + 4];
            pa[3] = Ps[(qrow0 + g + 8) * AS_STR + ks2 * 8 + t + 4];
            #pragma unroll
            for (int nf2 = 0; nf2 < 8; nf2++) {
                uint32_t bf[2];
                bf[0] = Vs[(ks2 * 8 + t    ) * AS_STR + nf2 * 8 + g];
                bf[1] = Vs[(ks2 * 8 + t + 4) * AS_STR + nf2 * 8 + g];
                mma_tf32(of[nf2], pa, bf);
            }
        }
        __syncwarp();
    }

    if (wb) {
        float inv0 = 1.f / rl0, inv1 = 1.f / rl1;
        #pragma unroll
        for (int nf = 0; nf < 8; nf++) {
            float* p0 = wfacc + (size_t)(qtok0 + g) * Cn + h * CH + nf * 8 + 2 * t;
            float* p1 = wfacc + (size_t)(qtok0 + g + 8) * Cn + h * CH + nf * 8 + 2 * t;
            float2 o0 = *(float2*)p0;
            float2 o1 = *(float2*)p1;
            o0.x += of[nf][0] * inv0; o0.y += of[nf][1] * inv0;
            o1.x += of[nf][2] * inv1; o1.y += of[nf][3] * inv1;
            *(float2*)p0 = o0;
            *(float2*)p1 = o1;
        }
    }
}

// ============================================================
// 5) global branch: depthwise conv -> LN -> exact GELU
// ============================================================
__global__ void convlngelu_kernel(const float* __restrict__ feat,
                                  const float* __restrict__ sr_w,
                                  const float* __restrict__ sr_b,
                                  const float* __restrict__ ln_g,
                                  const float* __restrict__ ln_b,
                                  float* __restrict__ g) {
    __shared__ float red[Cn];
    int bt = blockIdx.x;
    int b = bt >> 10, t = bt & 1023;
    int y1 = t >> 5, x1 = t & 31;
    int c = threadIdx.x;

    const float* src = feat + (((size_t)b * Cn + c) * Hn + y1 * SRn) * Wn + x1 * SRn;
    const float* w = sr_w + c * (SRn * SRn);
    float acc = sr_b[c];
    #pragma unroll
    for (int i = 0; i < SRn; i++)
        #pragma unroll
        for (int j = 0; j < SRn; j++)
            acc += src[i * Wn + j] * w[i * SRn + j];

    red[c] = acc;
    __syncthreads();
    for (int off = 128; off > 0; off >>= 1) {
        if (c < off) red[c] += red[c + off];
        __syncthreads();
    }
    float mu = red[0] * (1.f / Cn);
    __syncthreads();
    float dv = acc - mu;
    red[c] = dv * dv;
    __syncthreads();
    for (int off = 128; off > 0; off >>= 1) {
        if (c < off) red[c] += red[c + off];
        __syncthreads();
    }
    float var = red[0] * (1.f / Cn);
    float rs = rsqrtf(var + 1e-5f);
    float xh = dv * rs * ln_g[c] + ln_b[c];
    float gl = 0.5f * xh * (1.f + erff(xh * 0.70710678118654752440f));
    g[(size_t)bt * Cn + c] = gl;
}

// ============================================================
// 6) scatter-add projected windows back into out
// ============================================================
__global__ void scatter_kernel(const float* __restrict__ P, const int* __restrict__ sel,
                               float* __restrict__ out) {
    int n = blockIdx.x;
    int c = threadIdx.x;
    int b = n / NWF;
    int wi = sel[n];
    int wh = wi >> 5, ww = wi & 31;
    const float* src = P + (size_t)n * WINSZ * Cn + c;
    float* dst = out + (((size_t)b * Cn + c) * Hn + wh * WSZ) * Wn + ww * WSZ;
    #pragma unroll
    for (int p = 0; p < WINSZ; p++)
        dst[(p >> 3) * Wn + (p & 7)] += src[p * Cn];
}

// ============================================================
// launch
// ============================================================
extern "C" void kernel_launch(void* const* d_in, const int* in_sizes, int n_in,
                              void* d_out, int out_size) {
    const float* feat  = (const float*)d_in[0];
    const float* unc   = (const float*)d_in[1];
    const float* sr_w  = (const float*)d_in[2];
    const float* sr_b  = (const float*)d_in[3];
    const float* ln_g  = (const float*)d_in[4];
    const float* ln_b  = (const float*)d_in[5];
    const float* wq_l  = (const float*)d_in[6];
    const float* wkv_l = (const float*)d_in[7];
    const float* wq_g  = (const float*)d_in[8];
    const float* wkv_g = (const float*)d_in[9];
    const float* wp    = (const float*)d_in[10];
    const float* bp    = (const float*)d_in[11];
    float* out = (float*)d_out;

    float *wf, *q, *kv, *g;
    uint32_t *wtql, *wtkvl, *wtqg, *wtkvg, *wtp;
    int* sel;
    cudaGetSymbolAddress((void**)&wf,    d_wf);
    cudaGetSymbolAddress((void**)&q,     d_q);
    cudaGetSymbolAddress((void**)&kv,    d_kv);
    cudaGetSymbolAddress((void**)&g,     d_g);
    cudaGetSymbolAddress((void**)&sel,   d_sel);
    cudaGetSymbolAddress((void**)&wtql,  d_wtql);
    cudaGetSymbolAddress((void**)&wtkvl, d_wtkvl);
    cudaGetSymbolAddress((void**)&wtqg,  d_wtqg);
    cudaGetSymbolAddress((void**)&wtkvg, d_wtkvg);
    cudaGetSymbolAddress((void**)&wtp,   d_wtp);

    cudaFuncSetAttribute(mma_gemm_kernel, cudaFuncAttributeMaxDynamicSharedMemorySize, GEMM_SMEM);
    cudaFuncSetAttribute(attn_local_kernel, cudaFuncAttributeMaxDynamicSharedMemorySize, ATTL_SMEM);
    cudaFuncSetAttribute(attn_global_kernel, cudaFuncAttributeMaxDynamicSharedMemorySize, ATTG_SMEM);

    cudaMemcpyAsync(out, feat, (size_t)Bn * Cn * Hn * Wn * sizeof(float),
                    cudaMemcpyDeviceToDevice);

    transpose_all_kernel<<<dim3(8, 16, 5), dim3(32, 8)>>>(
        wq_l, wkv_l, wq_g, wkv_g, wp, wtql, wtkvl, wtqg, wtkvg, wtp);

    select_kernel<<<Bn, NWIN>>>(unc, sel);
    gather_kernel<<<NSEL, Cn>>>(feat, sel, wf);

    // local branch
    mma_gemm_kernel<<<dim3(NTOK / 128, 2), 256, GEMM_SMEM>>>(wf, wtql, q, nullptr, Cn);
    mma_gemm_kernel<<<dim3(NTOK / 128, 4), 256, GEMM_SMEM>>>(wf, wtkvl, kv, nullptr, 2 * Cn);
    attn_local_kernel<<<dim3(NSEL, HEADS), 128, ATTL_SMEM>>>(q, kv, wf);

    // global branch
    convlngelu_kernel<<<GTOK, Cn>>>(feat, sr_w, sr_b, ln_g, ln_b, g);
    mma_gemm_kernel<<<dim3(GTOK / 128, 4), 256, GEMM_SMEM>>>(g, wtkvg, kv, nullptr, 2 * Cn);

    mma_gemm_kernel<<<dim3(NTOK / 128, 2), 256, GEMM_SMEM>>>(wf, wtqg, q, nullptr, Cn);
    attn_global_kernel<<<dim3(Bn * PPB, HEADS), 256, ATTG_SMEM>>>(q, kv, wf);

    // projection + scatter
    mma_gemm_kernel<<<dim3(NTOK / 128, 2), 256, GEMM_SMEM>>>(wf, wtp, q, bp, Cn);
    scatter_kernel<<<NSEL, Cn>>>(q, sel, out);
}

// round 9
// speedup vs baseline: 1.2093x; 1.0013x over previous
#include <cuda_runtime.h>
#include <cuda_bf16.h>
#include <math.h>
#include <stdint.h>

// ---------------- problem constants ----------------
#define Bn      2
#define Cn      256
#define Hn      256
#define Wn      256
#define HEADS   4
#define CH      64
#define WSZ     8
#define NH      32
#define NWIN    1024
#define WINSZ   64
#define NWF     307
#define NSEL    614
#define SRn     8
#define H1      32
#define HW1     1024
#define NTOK    (NSEL*WINSZ)   // 39296
#define GTOK    (Bn*HW1)       // 2048
#define SCALE   0.125f
#define GK      256
#define PPB     154

// ---------------- scratch ----------------
__device__ float d_wf[NTOK * Cn];
__device__ float d_q [NTOK * Cn];
__device__ float d_kv[NTOK * 2 * Cn];
__device__ float d_g [GTOK * Cn];
__device__ int   d_sel[NSEL];
__device__ uint32_t d_wtql [Cn * Cn];      // tf32 bits, [n][k]
__device__ uint32_t d_wtkvl[2 * Cn * Cn];
__device__ uint32_t d_wtqg [Cn * Cn];
__device__ uint32_t d_wtkvg[2 * Cn * Cn];
__device__ uint32_t d_wtp  [Cn * Cn];

// ---------------- helpers ----------------
__device__ __forceinline__ uint32_t f2tf(float x) {
    uint32_t r;
    asm("cvt.rna.tf32.f32 %0, %1;" : "=r"(r) : "f"(x));
    return r;
}
__device__ __forceinline__ void mma_tf32(float d[4], const uint32_t a[4], const uint32_t b[2]) {
    asm volatile(
        "mma.sync.aligned.m16n8k8.row.col.f32.tf32.tf32.f32 "
        "{%0,%1,%2,%3}, {%4,%5,%6,%7}, {%8,%9}, {%0,%1,%2,%3};"
        : "+f"(d[0]), "+f"(d[1]), "+f"(d[2]), "+f"(d[3])
        : "r"(a[0]), "r"(a[1]), "r"(a[2]), "r"(a[3]), "r"(b[0]), "r"(b[1]));
}
__device__ __forceinline__ uint32_t smem_u32(const void* p) {
    uint32_t a;
    asm("{ .reg .u64 t; cvta.to.shared.u64 t, %1; cvt.u32.u64 %0, t; }" : "=r"(a) : "l"(p));
    return a;
}
__device__ __forceinline__ void cp_async16(uint32_t saddr, const void* g) {
    asm volatile("cp.async.cg.shared.global [%0], [%1], 16;" :: "r"(saddr), "l"(g));
}
#define CP_COMMIT() asm volatile("cp.async.commit_group;" ::: "memory")
#define CP_WAIT0()  asm volatile("cp.async.wait_group 0;" ::: "memory")
#define CP_WAIT1()  asm volatile("cp.async.wait_group 1;" ::: "memory")

// ============================================================
// 0) weight transpose + tf32 pre-round: WT[n][k] = tf32(W[k][n])
// ============================================================
__global__ void transpose_all_kernel(
    const float* __restrict__ w0, const float* __restrict__ w1,
    const float* __restrict__ w2, const float* __restrict__ w3,
    const float* __restrict__ w4,
    uint32_t* __restrict__ t0, uint32_t* __restrict__ t1,
    uint32_t* __restrict__ t2, uint32_t* __restrict__ t3,
    uint32_t* __restrict__ t4) {
    __shared__ float t[32][33];
    const float* W; uint32_t* WT; int N;
    switch (blockIdx.z) {
        case 0:  W = w0; WT = t0; N = Cn;     break;
        case 1:  W = w1; WT = t1; N = 2 * Cn; break;
        case 2:  W = w2; WT = t2; N = Cn;     break;
        case 3:  W = w3; WT = t3; N = 2 * Cn; break;
        default: W = w4; WT = t4; N = Cn;     break;
    }
    int kx = blockIdx.x * 32, nx = blockIdx.y * 32;
    if (nx >= N) return;
    for (int r = threadIdx.y; r < 32; r += 8)
        t[r][threadIdx.x] = W[(size_t)(kx + r) * N + nx + threadIdx.x];
    __syncthreads();
    for (int r = threadIdx.y; r < 32; r += 8)
        WT[(size_t)(nx + r) * GK + kx + threadIdx.x] = f2tf(t[threadIdx.x][r]);
}

// ============================================================
// 1) top-k window selection
// ============================================================
__global__ void select_kernel(const float* __restrict__ unc, int* __restrict__ sel) {
    __shared__ float sc[NWIN];
    int b  = blockIdx.x;
    int wi = threadIdx.x;
    int wh = wi >> 5, ww = wi & 31;
    const float* u = unc + ((size_t)b * Hn + wh * WSZ) * Wn + ww * WSZ;
    float s = 0.f;
    #pragma unroll
    for (int i = 0; i < WSZ; i++)
        #pragma unroll
        for (int j = 0; j < WSZ; j++)
            s += u[i * Wn + j];
    sc[wi] = s;
    __syncthreads();
    int rank = 0;
    for (int j = 0; j < NWIN; j++) {
        float sj = sc[j];
        rank += (sj > s) || (sj == s && j < wi);
    }
    if (rank < NWF) sel[b * NWF + rank] = wi;
}

// ============================================================
// 2) gather selected windows
// ============================================================
__global__ void gather_kernel(const float* __restrict__ feat, const int* __restrict__ sel,
                              float* __restrict__ wf) {
    int n = blockIdx.x;
    int c = threadIdx.x;
    int b = n / NWF;
    int wi = sel[n];
    int wh = wi >> 5, ww = wi & 31;
    const float* src = feat + (((size_t)b * Cn + c) * Hn + wh * WSZ) * Wn + ww * WSZ;
    float* dst = wf + (size_t)n * WINSZ * Cn + c;
    #pragma unroll
    for (int p = 0; p < WINSZ; p++)
        dst[p * Cn] = src[(p >> 3) * Wn + (p & 7)];
}

// ============================================================
// 3) tf32 mma.sync GEMM, 128x128 tile, BK=32, cp.async 2-stage
//    8 warps = 2m x 4n; warp = 64x32 = 4x4 fragments
// ============================================================
#define ASTG (128 * 36)
#define GEMM_SMEM (4 * ASTG * 4)   // 73728 bytes

__global__ __launch_bounds__(256)
void mma_gemm_kernel(const float* __restrict__ A, const uint32_t* __restrict__ WT,
                     float* __restrict__ C, const float* __restrict__ bias, int ldc) {
    extern __shared__ uint32_t sg[];
    int tid = threadIdx.x;
    int lane = tid & 31, wid = tid >> 5;
    int g = lane >> 2, t = lane & 3;
    int wm = wid & 1, wn = wid >> 1;
    int m0 = blockIdx.x * 128, n0 = blockIdx.y * 128;

    uint32_t sbase = smem_u32(sg);

    // chunk coords for this thread (4 chunks of 16B each for A and B per stage)
    int crow[4], cq4[4];
    #pragma unroll
    for (int u = 0; u < 4; u++) {
        int c = tid + u * 256;
        crow[u] = c >> 3;
        cq4[u]  = (c & 7) << 2;
    }

    // stage loader
    auto load_stage = [&](int kc, int buf) {
        uint32_t a_s = sbase + (uint32_t)(buf * ASTG) * 4u;
        uint32_t b_s = sbase + (uint32_t)((2 + buf) * ASTG) * 4u;
        #pragma unroll
        for (int u = 0; u < 4; u++) {
            int row = crow[u], q4 = cq4[u];
            cp_async16(a_s + (uint32_t)(row * 36 + q4) * 4u,
                       A + (size_t)(m0 + row) * GK + kc + q4);
            cp_async16(b_s + (uint32_t)(row * 36 + q4) * 4u,
                       WT + (size_t)(n0 + row) * GK + kc + q4);
        }
    };

    float acc[4][4][4] = {};

    load_stage(0, 0);
    CP_COMMIT();

    #pragma unroll 1
    for (int st = 0; st < 8; st++) {
        if (st < 7) {
            load_stage((st + 1) * 32, (st + 1) & 1);
            CP_COMMIT();
            CP_WAIT1();
        } else {
            CP_WAIT0();
        }
        __syncthreads();

        const uint32_t* Asb = sg + (st & 1) * ASTG;
        const uint32_t* Bsb = sg + (2 + (st & 1)) * ASTG;

        #pragma unroll
        for (int ks = 0; ks < 4; ks++) {
            uint32_t af[4][4];
            #pragma unroll
            for (int mf = 0; mf < 4; mf++) {
                int rb = wm * 64 + mf * 16;
                af[mf][0] = f2tf(__uint_as_float(Asb[(rb + g    ) * 36 + ks * 8 + t    ]));
                af[mf][1] = f2tf(__uint_as_float(Asb[(rb + g + 8) * 36 + ks * 8 + t    ]));
                af[mf][2] = f2tf(__uint_as_float(Asb[(rb + g    ) * 36 + ks * 8 + t + 4]));
                af[mf][3] = f2tf(__uint_as_float(Asb[(rb + g + 8) * 36 + ks * 8 + t + 4]));
            }
            #pragma unroll
            for (int nf = 0; nf < 4; nf++) {
                int nb = wn * 32 + nf * 8;
                uint32_t bf[2];
                bf[0] = Bsb[(nb + g) * 36 + ks * 8 + t];
                bf[1] = Bsb[(nb + g) * 36 + ks * 8 + t + 4];
                #pragma unroll
                for (int mf = 0; mf < 4; mf++)
                    mma_tf32(acc[mf][nf], af[mf], bf);
            }
        }
        __syncthreads();
    }

    #pragma unroll
    for (int mf = 0; mf < 4; mf++) {
        int r0 = m0 + wm * 64 + mf * 16 + g;
        #pragma unroll
        for (int nf = 0; nf < 4; nf++) {
            int cc = n0 + wn * 32 + nf * 8 + 2 * t;
            float b0 = 0.f, b1 = 0.f;
            if (bias) { b0 = __ldg(&bias[cc]); b1 = __ldg(&bias[cc + 1]); }
            float2 v0 = { acc[mf][nf][0] + b0, acc[mf][nf][1] + b1 };
            float2 v1 = { acc[mf][nf][2] + b0, acc[mf][nf][3] + b1 };
            *(float2*)(C + (size_t)r0 * ldc + cc)       = v0;
            *(float2*)(C + (size_t)(r0 + 8) * ldc + cc) = v1;
        }
    }
}

// ============================================================
// 4a) local window attention (tf32 mma), 128 threads, 1 window
// ============================================================
#define AS_STR 68
#define ATTL_SMEM (3 * 64 * AS_STR * 4)

__global__ __launch_bounds__(128)
void attn_local_kernel(const float* __restrict__ Q, const float* __restrict__ KV,
                       float* __restrict__ wfacc) {
    extern __shared__ uint32_t smu[];
    uint32_t* Ks = smu;
    uint32_t* Vs = Ks + 64 * AS_STR;
    uint32_t* Ps = Vs + 64 * AS_STR;

    int n = blockIdx.x, h = blockIdx.y;
    int tid = threadIdx.x;
    int lane = tid & 31, w = tid >> 5;
    int g = lane >> 2, t = lane & 3;
    int qtok0 = n * WINSZ;
    int qrow0 = w * 16;

    uint32_t qf[8][4];
    {
        const float* qb = Q + (size_t)(qtok0 + qrow0) * Cn + h * CH;
        #pragma unroll
        for (int ks = 0; ks < 8; ks++) {
            qf[ks][0] = f2tf(qb[(size_t)(g    ) * Cn + ks * 8 + t    ] * SCALE);
            qf[ks][1] = f2tf(qb[(size_t)(g + 8) * Cn + ks * 8 + t    ] * SCALE);
            qf[ks][2] = f2tf(qb[(size_t)(g    ) * Cn + ks * 8 + t + 4] * SCALE);
            qf[ks][3] = f2tf(qb[(size_t)(g + 8) * Cn + ks * 8 + t + 4] * SCALE);
        }
    }

    for (int i = tid; i < 1024; i += 128) {
        int tok = i >> 4, c4 = (i & 15) << 2;
        const float* base = KV + (size_t)(qtok0 + tok) * (2 * Cn) + h * CH;
        float4 kv4 = *(const float4*)(base + c4);
        float4 vv4 = *(const float4*)(base + Cn + c4);
        uint4 kk = { f2tf(kv4.x), f2tf(kv4.y), f2tf(kv4.z), f2tf(kv4.w) };
        uint4 vv = { f2tf(vv4.x), f2tf(vv4.y), f2tf(vv4.z), f2tf(vv4.w) };
        *(uint4*)(Ks + tok * AS_STR + c4) = kk;
        *(uint4*)(Vs + tok * AS_STR + c4) = vv;
    }
    __syncthreads();

    float ss[8][4] = {};
    #pragma unroll
    for (int nf = 0; nf < 8; nf++) {
        #pragma unroll
        for (int ks = 0; ks < 8; ks++) {
            uint32_t bf[2];
            bf[0] = Ks[(nf * 8 + g) * AS_STR + ks * 8 + t];
            bf[1] = Ks[(nf * 8 + g) * AS_STR + ks * 8 + t + 4];
            mma_tf32(ss[nf], qf[ks], bf);
        }
    }

    float cm0 = -1e30f, cm1 = -1e30f;
    #pragma unroll
    for (int nf = 0; nf < 8; nf++) {
        cm0 = fmaxf(cm0, fmaxf(ss[nf][0], ss[nf][1]));
        cm1 = fmaxf(cm1, fmaxf(ss[nf][2], ss[nf][3]));
    }
    cm0 = fmaxf(cm0, __shfl_xor_sync(0xffffffffu, cm0, 1));
    cm0 = fmaxf(cm0, __shfl_xor_sync(0xffffffffu, cm0, 2));
    cm1 = fmaxf(cm1, __shfl_xor_sync(0xffffffffu, cm1, 1));
    cm1 = fmaxf(cm1, __shfl_xor_sync(0xffffffffu, cm1, 2));
    float sum0 = 0.f, sum1 = 0.f;
    #pragma unroll
    for (int nf = 0; nf < 8; nf++) {
        ss[nf][0] = __expf(ss[nf][0] - cm0);
        ss[nf][1] = __expf(ss[nf][1] - cm0);
        ss[nf][2] = __expf(ss[nf][2] - cm1);
        ss[nf][3] = __expf(ss[nf][3] - cm1);
        sum0 += ss[nf][0] + ss[nf][1];
        sum1 += ss[nf][2] + ss[nf][3];
    }
    sum0 += __shfl_xor_sync(0xffffffffu, sum0, 1);
    sum0 += __shfl_xor_sync(0xffffffffu, sum0, 2);
    sum1 += __shfl_xor_sync(0xffffffffu, sum1, 1);
    sum1 += __shfl_xor_sync(0xffffffffu, sum1, 2);

    #pragma unroll
    for (int nf = 0; nf < 8; nf++) {
        int pc = nf * 8 + 2 * t;
        uint2 p0 = { f2tf(ss[nf][0]), f2tf(ss[nf][1]) };
        uint2 p1 = { f2tf(ss[nf][2]), f2tf(ss[nf][3]) };
        *(uint2*)(Ps + (qrow0 + g) * AS_STR + pc)     = p0;
        *(uint2*)(Ps + (qrow0 + g + 8) * AS_STR + pc) = p1;
    }
    __syncwarp();

    float of[8][4] = {};
    #pragma unroll
    for (int ks2 = 0; ks2 < 8; ks2++) {
        uint32_t pa[4];
        pa[0] = Ps[(qrow0 + g    ) * AS_STR + ks2 * 8 + t];
        pa[1] = Ps[(qrow0 + g + 8) * AS_STR + ks2 * 8 + t];
        pa[2] = Ps[(qrow0 + g    ) * AS_STR + ks2 * 8 + t + 4];
        pa[3] = Ps[(qrow0 + g + 8) * AS_STR + ks2 * 8 + t + 4];
        #pragma unroll
        for (int nf2 = 0; nf2 < 8; nf2++) {
            uint32_t bf[2];
            bf[0] = Vs[(ks2 * 8 + t    ) * AS_STR + nf2 * 8 + g];
            bf[1] = Vs[(ks2 * 8 + t + 4) * AS_STR + nf2 * 8 + g];
            mma_tf32(of[nf2], pa, bf);
        }
    }

    float inv0 = 1.f / sum0, inv1 = 1.f / sum1;
    #pragma unroll
    for (int nf = 0; nf < 8; nf++) {
        float* p0 = wfacc + (size_t)(qtok0 + qrow0 + g) * Cn + h * CH + nf * 8 + 2 * t;
        float* p1 = wfacc + (size_t)(qtok0 + qrow0 + g + 8) * Cn + h * CH + nf * 8 + 2 * t;
        float2 o0 = *(float2*)p0;
        float2 o1 = *(float2*)p1;
        o0.x += of[nf][0] * inv0; o0.y += of[nf][1] * inv0;
        o1.x += of[nf][2] * inv1; o1.y += of[nf][3] * inv1;
        *(float2*)p0 = o0;
        *(float2*)p1 = o1;
    }
}

// ============================================================
// 4b) global cross-attention: 2 windows / block, 256 threads
// ============================================================
#define ATTG_SMEM ((64 + 64 + 128) * AS_STR * 4)

__global__ __launch_bounds__(256)
void attn_global_kernel(const float* __restrict__ Q, const float* __restrict__ KV,
                        float* __restrict__ wfacc) {
    extern __shared__ uint32_t smu[];
    uint32_t* Ks = smu;
    uint32_t* Vs = Ks + 64 * AS_STR;
    uint32_t* Ps = Vs + 64 * AS_STR;

    int b = blockIdx.x / PPB, pb = blockIdx.x % PPB;
    int h = blockIdx.y;
    int s0 = b * NWF + pb * 2;
    bool has2 = (pb * 2 + 1) < NWF;

    int tid = threadIdx.x;
    int lane = tid & 31, w = tid >> 5;
    int g = lane >> 2, t = lane & 3;
    int qrow0 = w * 16;
    int myslot = (qrow0 < 64) ? s0 : (has2 ? s0 + 1 : s0);
    bool wb = (qrow0 < 64) || has2;
    int qtok0 = myslot * WINSZ + (qrow0 & 63);
    int kbase = b * HW1;

    uint32_t qf[8][4];
    {
        const float* qb = Q + (size_t)qtok0 * Cn + h * CH;
        #pragma unroll
        for (int ks = 0; ks < 8; ks++) {
            qf[ks][0] = f2tf(qb[(size_t)(g    ) * Cn + ks * 8 + t    ] * SCALE);
            qf[ks][1] = f2tf(qb[(size_t)(g + 8) * Cn + ks * 8 + t    ] * SCALE);
            qf[ks][2] = f2tf(qb[(size_t)(g    ) * Cn + ks * 8 + t + 4] * SCALE);
            qf[ks][3] = f2tf(qb[(size_t)(g + 8) * Cn + ks * 8 + t + 4] * SCALE);
        }
    }

    float of[8][4] = {};
    float rm0 = -1e30f, rm1 = -1e30f, rl0 = 0.f, rl1 = 0.f;

    for (int chk = 0; chk < 16; chk++) {
        __syncthreads();
        for (int i = tid; i < 1024; i += 256) {
            int tok = i >> 4, c4 = (i & 15) << 2;
            const float* base = KV + (size_t)(kbase + chk * 64 + tok) * (2 * Cn) + h * CH;
            float4 kv4 = *(const float4*)(base + c4);
            float4 vv4 = *(const float4*)(base + Cn + c4);
            uint4 kk = { f2tf(kv4.x), f2tf(kv4.y), f2tf(kv4.z), f2tf(kv4.w) };
            uint4 vv = { f2tf(vv4.x), f2tf(vv4.y), f2tf(vv4.z), f2tf(vv4.w) };
            *(uint4*)(Ks + tok * AS_STR + c4) = kk;
            *(uint4*)(Vs + tok * AS_STR + c4) = vv;
        }
        __syncthreads();

        float ss[8][4] = {};
        #pragma unroll
        for (int nf = 0; nf < 8; nf++) {
            #pragma unroll
            for (int ks = 0; ks < 8; ks++) {
                uint32_t bf[2];
                bf[0] = Ks[(nf * 8 + g) * AS_STR + ks * 8 + t];
                bf[1] = Ks[(nf * 8 + g) * AS_STR + ks * 8 + t + 4];
                mma_tf32(ss[nf], qf[ks], bf);
            }
        }

        float cm0 = -1e30f, cm1 = -1e30f;
        #pragma unroll
        for (int nf = 0; nf < 8; nf++) {
            cm0 = fmaxf(cm0, fmaxf(ss[nf][0], ss[nf][1]));
            cm1 = fmaxf(cm1, fmaxf(ss[nf][2], ss[nf][3]));
        }
        cm0 = fmaxf(cm0, __shfl_xor_sync(0xffffffffu, cm0, 1));
        cm0 = fmaxf(cm0, __shfl_xor_sync(0xffffffffu, cm0, 2));
        cm1 = fmaxf(cm1, __shfl_xor_sync(0xffffffffu, cm1, 1));
        cm1 = fmaxf(cm1, __shfl_xor_sync(0xffffffffu, cm1, 2));
        float nm0 = fmaxf(rm0, cm0), nm1 = fmaxf(rm1, cm1);
        float scl0 = __expf(rm0 - nm0), scl1 = __expf(rm1 - nm1);
        float sum0 = 0.f, sum1 = 0.f;
        #pragma unroll
        for (int nf = 0; nf < 8; nf++) {
            ss[nf][0] = __expf(ss[nf][0] - nm0);
            ss[nf][1] = __expf(ss[nf][1] - nm0);
            ss[nf][2] = __expf(ss[nf][2] - nm1);
            ss[nf][3] = __expf(ss[nf][3] - nm1);
            sum0 += ss[nf][0] + ss[nf][1];
            sum1 += ss[nf][2] + ss[nf][3];
        }
        sum0 += __shfl_xor_sync(0xffffffffu, sum0, 1);
        sum0 += __shfl_xor_sync(0xffffffffu, sum0, 2);
        sum1 += __shfl_xor_sync(0xffffffffu, sum1, 1);
        sum1 += __shfl_xor_sync(0xffffffffu, sum1, 2);
        rl0 = rl0 * scl0 + sum0;  rm0 = nm0;
        rl1 = rl1 * scl1 + sum1;  rm1 = nm1;
        #pragma unroll
        for (int nf = 0; nf < 8; nf++) {
            of[nf][0] *= scl0; of[nf][1] *= scl0;
            of[nf][2] *= scl1; of[nf][3] *= scl1;
        }

        #pragma unroll
        for (int nf = 0; nf < 8; nf++) {
            int pc = nf * 8 + 2 * t;
            uint2 p0 = { f2tf(ss[nf][0]), f2tf(ss[nf][1]) };
            uint2 p1 = { f2tf(ss[nf][2]), f2tf(ss[nf][3]) };
            *(uint2*)(Ps + (qrow0 + g) * AS_STR + pc)     = p0;
            *(uint2*)(Ps + (qrow0 + g + 8) * AS_STR + pc) = p1;
        }
        __syncwarp();

        #pragma unroll
        for (int ks2 = 0; ks2 < 8; ks2++) {
            uint32_t pa[4];
            pa[0] = Ps[(qrow0 + g    ) * AS_STR + ks2 * 8 + t];
            pa[1] = Ps[(qrow0 + g + 8) * AS_STR + ks2 * 8 + t];
            pa[2] = Ps[(qrow0 + g    ) * AS_STR + ks2 * 8 + t + 4];
            pa[3] = Ps[(qrow0 + g + 8) * AS_STR + ks2 * 8 + t + 4];
            #pragma unroll
            for (int nf2 = 0; nf2 < 8; nf2++) {
                uint32_t bf[2];
                bf[0] = Vs[(ks2 * 8 + t    ) * AS_STR + nf2 * 8 + g];
                bf[1] = Vs[(ks2 * 8 + t + 4) * AS_STR + nf2 * 8 + g];
                mma_tf32(of[nf2], pa, bf);
            }
        }
        __syncwarp();
    }

    if (wb) {
        float inv0 = 1.f / rl0, inv1 = 1.f / rl1;
        #pragma unroll
        for (int nf = 0; nf < 8; nf++) {
            float* p0 = wfacc + (size_t)(qtok0 + g) * Cn + h * CH + nf * 8 + 2 * t;
            float* p1 = wfacc + (size_t)(qtok0 + g + 8) * Cn + h * CH + nf * 8 + 2 * t;
            float2 o0 = *(float2*)p0;
            float2 o1 = *(float2*)p1;
            o0.x += of[nf][0] * inv0; o0.y += of[nf][1] * inv0;
            o1.x += of[nf][2] * inv1; o1.y += of[nf][3] * inv1;
            *(float2*)p0 = o0;
            *(float2*)p1 = o1;
        }
    }
}

// ============================================================
// 5) global branch: depthwise conv -> LN -> exact GELU
// ============================================================
__global__ void convlngelu_kernel(const float* __restrict__ feat,
                                  const float* __restrict__ sr_w,
                                  const float* __restrict__ sr_b,
                                  const float* __restrict__ ln_g,
                                  const float* __restrict__ ln_b,
                                  float* __restrict__ g) {
    __shared__ float red[Cn];
    int bt = blockIdx.x;
    int b = bt >> 10, t = bt & 1023;
    int y1 = t >> 5, x1 = t & 31;
    int c = threadIdx.x;

    const float* src = feat + (((size_t)b * Cn + c) * Hn + y1 * SRn) * Wn + x1 * SRn;
    const float* w = sr_w + c * (SRn * SRn);
    float acc = sr_b[c];
    #pragma unroll
    for (int i = 0; i < SRn; i++)
        #pragma unroll
        for (int j = 0; j < SRn; j++)
            acc += src[i * Wn + j] * w[i * SRn + j];

    red[c] = acc;
    __syncthreads();
    for (int off = 128; off > 0; off >>= 1) {
        if (c < off) red[c] += red[c + off];
        __syncthreads();
    }
    float mu = red[0] * (1.f / Cn);
    __syncthreads();
    float dv = acc - mu;
    red[c] = dv * dv;
    __syncthreads();
    for (int off = 128; off > 0; off >>= 1) {
        if (c < off) red[c] += red[c + off];
        __syncthreads();
    }
    float var = red[0] * (1.f / Cn);
    float rs = rsqrtf(var + 1e-5f);
    float xh = dv * rs * ln_g[c] + ln_b[c];
    float gl = 0.5f * xh * (1.f + erff(xh * 0.70710678118654752440f));
    g[(size_t)bt * Cn + c] = gl;
}

// ============================================================
// 6) scatter-add projected windows back into out
// ============================================================
__global__ void scatter_kernel(const float* __restrict__ P, const int* __restrict__ sel,
                               float* __restrict__ out) {
    int n = blockIdx.x;
    int c = threadIdx.x;
    int b = n / NWF;
    int wi = sel[n];
    int wh = wi >> 5, ww = wi & 31;
    const float* src = P + (size_t)n * WINSZ * Cn + c;
    float* dst = out + (((size_t)b * Cn + c) * Hn + wh * WSZ) * Wn + ww * WSZ;
    #pragma unroll
    for (int p = 0; p < WINSZ; p++)
        dst[(p >> 3) * Wn + (p & 7)] += src[p * Cn];
}

// ============================================================
// launch
// ============================================================
extern "C" void kernel_launch(void* const* d_in, const int* in_sizes, int n_in,
                              void* d_out, int out_size) {
    const float* feat  = (const float*)d_in[0];
    const float* unc   = (const float*)d_in[1];
    const float* sr_w  = (const float*)d_in[2];
    const float* sr_b  = (const float*)d_in[3];
    const float* ln_g  = (const float*)d_in[4];
    const float* ln_b  = (const float*)d_in[5];
    const float* wq_l  = (const float*)d_in[6];
    const float* wkv_l = (const float*)d_in[7];
    const float* wq_g  = (const float*)d_in[8];
    const float* wkv_g = (const float*)d_in[9];
    const float* wp    = (const float*)d_in[10];
    const float* bp    = (const float*)d_in[11];
    float* out = (float*)d_out;

    float *wf, *q, *kv, *g;
    uint32_t *wtql, *wtkvl, *wtqg, *wtkvg, *wtp;
    int* sel;
    cudaGetSymbolAddress((void**)&wf,    d_wf);
    cudaGetSymbolAddress((void**)&q,     d_q);
    cudaGetSymbolAddress((void**)&kv,    d_kv);
    cudaGetSymbolAddress((void**)&g,     d_g);
    cudaGetSymbolAddress((void**)&sel,   d_sel);
    cudaGetSymbolAddress((void**)&wtql,  d_wtql);
    cudaGetSymbolAddress((void**)&wtkvl, d_wtkvl);
    cudaGetSymbolAddress((void**)&wtqg,  d_wtqg);
    cudaGetSymbolAddress((void**)&wtkvg, d_wtkvg);
    cudaGetSymbolAddress((void**)&wtp,   d_wtp);

    cudaFuncSetAttribute(mma_gemm_kernel, cudaFuncAttributeMaxDynamicSharedMemorySize, GEMM_SMEM);
    cudaFuncSetAttribute(attn_local_kernel, cudaFuncAttributeMaxDynamicSharedMemorySize, ATTL_SMEM);
    cudaFuncSetAttribute(attn_global_kernel, cudaFuncAttributeMaxDynamicSharedMemorySize, ATTG_SMEM);

    cudaMemcpyAsync(out, feat, (size_t)Bn * Cn * Hn * Wn * sizeof(float),
                    cudaMemcpyDeviceToDevice);

    transpose_all_kernel<<<dim3(8, 16, 5), dim3(32, 8)>>>(
        wq_l, wkv_l, wq_g, wkv_g, wp, wtql, wtkvl, wtqg, wtkvg, wtp);

    select_kernel<<<Bn, NWIN>>>(unc, sel);
    gather_kernel<<<NSEL, Cn>>>(feat, sel, wf);

    // local branch
    mma_gemm_kernel<<<dim3(NTOK / 128, 2), 256, GEMM_SMEM>>>(wf, wtql, q, nullptr, Cn);
    mma_gemm_kernel<<<dim3(NTOK / 128, 4), 256, GEMM_SMEM>>>(wf, wtkvl, kv, nullptr, 2 * Cn);
    attn_local_kernel<<<dim3(NSEL, HEADS), 128, ATTL_SMEM>>>(q, kv, wf);

    // global branch
    convlngelu_kernel<<<GTOK, Cn>>>(feat, sr_w, sr_b, ln_g, ln_b, g);
    mma_gemm_kernel<<<dim3(GTOK / 128, 4), 256, GEMM_SMEM>>>(g, wtkvg, kv, nullptr, 2 * Cn);

    mma_gemm_kernel<<<dim3(NTOK / 128, 2), 256, GEMM_SMEM>>>(wf, wtqg, q, nullptr, Cn);
    attn_global_kernel<<<dim3(Bn * PPB, HEADS), 256, ATTG_SMEM>>>(q, kv, wf);

    // projection + scatter
    mma_gemm_kernel<<<dim3(NTOK / 128, 2), 256, GEMM_SMEM>>>(wf, wtp, q, bp, Cn);
    scatter_kernel<<<NSEL, Cn>>>(q, sel, out);
}